// round 5
// baseline (speedup 1.0000x reference)
#include <cuda_runtime.h>

// Problem constants
constexpr int Bc   = 2;
constexpr int Sc   = 2048;
constexpr int HIDc = 1024;
constexpr int NHc  = 16;
constexpr int HDc  = 64;           // HID / NH
constexpr int Mtot = Bc * Sc;      // 4096
constexpr size_t CHUNK = (size_t)Bc * Sc * HIDc;  // 4,194,304 floats
constexpr int NROWS = Bc * NHc * Sc;              // 65536 softmax rows

// Scratch: [0]=Q, [1]=K, [2]=V, [3]=ctx (attn @ V, in [B,S,HID] layout)
__device__ float g_buf[4 * CHUNK];
__device__ float g_rowsum[NROWS];

// ---------------------------------------------------------------------------
// Zero the rowsum accumulator (must happen every replay; atomics accumulate).
// ---------------------------------------------------------------------------
__global__ void zero_rowsum_kernel()
{
    const int i = blockIdx.x * blockDim.x + threadIdx.x;
    ((float4*)g_rowsum)[i] = make_float4(0.f, 0.f, 0.f, 0.f);
}

// ---------------------------------------------------------------------------
// SGEMM NT + bias: C[m,n] = sum_k A[m,k] * W[n,k] + bias[n]
// BM=128, BN=64, BK=16, 256 threads, 8x4 per thread. Grid = (N/64, M/128).
// ---------------------------------------------------------------------------
__global__ __launch_bounds__(256) void sgemm_nt_bias(
    const float* __restrict__ Aext, int a_sel,
    const float* __restrict__ W, const float* __restrict__ bias,
    float* __restrict__ Cext, int c_sel,
    int M, int N, int K)
{
    const float* A = (a_sel >= 0) ? (const float*)(g_buf + (size_t)a_sel * CHUNK) : Aext;
    float*       C = (c_sel >= 0) ? (g_buf + (size_t)c_sel * CHUNK) : Cext;

    constexpr int BM = 128, BN = 64, BK = 16, TM = 8, TN = 4;
    __shared__ float As[BK][BM + 4];
    __shared__ float Ws[BK][BN + 4];

    const int tid = threadIdx.x;
    const int tx = tid & 15, ty = tid >> 4;     // 16 x 16 thread grid
    const int bm = blockIdx.y * BM, bn = blockIdx.x * BN;

    // A loads: 128 rows x 16 cols = 512 float4, 2 per thread.
    const int ar = tid >> 1;            // 0..127  (two float4 per row pattern)
    const int ac = (tid & 1) * 8;       // 0 or 8 -> two float4 at ac, ac+4? no:
    // simpler: e-based below.

    // W loads: 64 rows x 16 cols = 256 float4, 1 per thread.
    const int wr = tid >> 2;            // 0..63
    const int wc = (tid & 3) * 4;       // 0,4,8,12

    float acc[TM][TN];
    #pragma unroll
    for (int i = 0; i < TM; i++)
        #pragma unroll
        for (int j = 0; j < TN; j++) acc[i][j] = 0.0f;

    for (int k0 = 0; k0 < K; k0 += BK) {
        #pragma unroll
        for (int L = 0; L < 2; L++) {
            const int e = tid + L * 256;
            const int r = e >> 2;             // 0..127
            const int c = (e & 3) * 4;        // 0,4,8,12
            float4 av = *(const float4*)(A + (size_t)(bm + r) * K + k0 + c);
            As[c + 0][r] = av.x; As[c + 1][r] = av.y;
            As[c + 2][r] = av.z; As[c + 3][r] = av.w;
        }
        {
            float4 wv = *(const float4*)(W + (size_t)(bn + wr) * K + k0 + wc);
            Ws[wc + 0][wr] = wv.x; Ws[wc + 1][wr] = wv.y;
            Ws[wc + 2][wr] = wv.z; Ws[wc + 3][wr] = wv.w;
        }
        __syncthreads();
        #pragma unroll
        for (int kk = 0; kk < BK; kk++) {
            float a[TM], b[TN];
            *(float4*)&a[0] = *(const float4*)&As[kk][ty * TM];
            *(float4*)&a[4] = *(const float4*)&As[kk][ty * TM + 4];
            *(float4*)&b[0] = *(const float4*)&Ws[kk][tx * TN];
            #pragma unroll
            for (int i = 0; i < TM; i++)
                #pragma unroll
                for (int j = 0; j < TN; j++)
                    acc[i][j] = fmaf(a[i], b[j], acc[i][j]);
        }
        __syncthreads();
    }

    const int n = bn + tx * TN;
    const float4 bv = *(const float4*)(bias + n);
    #pragma unroll
    for (int i = 0; i < TM; i++) {
        const int m = bm + ty * TM + i;
        float4 o;
        o.x = acc[i][0] + bv.x;
        o.y = acc[i][1] + bv.y;
        o.z = acc[i][2] + bv.z;
        o.w = acc[i][3] + bv.w;
        *(float4*)(C + (size_t)m * N + n) = o;
    }
}

// ---------------------------------------------------------------------------
// Scores+exp: attn[b,h,q,k] = exp( (Q.K)/8 + beta*sim ), masked -> 0.
// 64x64 tile per block (the empirically ~67 TF/s config), 4x4 per thread.
// Accumulates per-row partial sums of exp into g_rowsum via atomics
// (softmax shift c=0 is exact; scores are O(10) so fp32 exp cannot overflow).
// ---------------------------------------------------------------------------
__global__ __launch_bounds__(256) void scores_exp_kernel(
    const float* __restrict__ sim, const int* __restrict__ amask,
    const float* __restrict__ beta_p, float* __restrict__ attn)
{
    const float* Q  = g_buf;
    const float* Kh = g_buf + CHUNK;

    constexpr int BQ = 64, BKt = 64, BD = 16;
    __shared__ float Qs[BD][BQ + 4];
    __shared__ float Ks[BD][BKt + 4];
    __shared__ float red[BQ][17];

    const int bh = blockIdx.z, b = bh >> 4, h = bh & 15;
    const int q0 = blockIdx.y * BQ, k0 = blockIdx.x * BKt;
    const int tid = threadIdx.x, tx = tid & 15, ty = tid >> 4;

    const int lrow = tid >> 2;        // 0..63
    const int lcol = (tid & 3) * 4;   // 0,4,8,12
    const size_t qbase = ((size_t)b * Sc + q0 + lrow) * HIDc + h * HDc + lcol;
    const size_t kbase = ((size_t)b * Sc + k0 + lrow) * HIDc + h * HDc + lcol;

    float acc[4][4] = {};

    #pragma unroll
    for (int d0 = 0; d0 < HDc; d0 += BD) {
        float4 qv = *(const float4*)(Q + qbase + d0);
        float4 kv = *(const float4*)(Kh + kbase + d0);
        Qs[lcol + 0][lrow] = qv.x; Qs[lcol + 1][lrow] = qv.y;
        Qs[lcol + 2][lrow] = qv.z; Qs[lcol + 3][lrow] = qv.w;
        Ks[lcol + 0][lrow] = kv.x; Ks[lcol + 1][lrow] = kv.y;
        Ks[lcol + 2][lrow] = kv.z; Ks[lcol + 3][lrow] = kv.w;
        __syncthreads();
        #pragma unroll
        for (int kk = 0; kk < BD; kk++) {
            float a[4], c[4];
            *(float4*)a = *(const float4*)&Qs[kk][ty * 4];
            *(float4*)c = *(const float4*)&Ks[kk][tx * 4];
            #pragma unroll
            for (int i = 0; i < 4; i++)
                #pragma unroll
                for (int j = 0; j < 4; j++)
                    acc[i][j] = fmaf(a[i], c[j], acc[i][j]);
        }
        __syncthreads();
    }

    const float beta = *beta_p;
    const float scale = 0.125f;  // 1/sqrt(64)
    const int kcol = k0 + tx * 4;
    const int4 m4 = *(const int4*)(amask + (size_t)b * Sc + kcol);

    float rsum[4];
    #pragma unroll
    for (int i = 0; i < 4; i++) {
        const int q = q0 + ty * 4 + i;
        const float4 sv = *(const float4*)(sim + ((size_t)b * Sc + q) * Sc + kcol);
        float4 o;
        o.x = (m4.x == 0) ? 0.0f : __expf(fmaf(beta, sv.x, acc[i][0] * scale));
        o.y = (m4.y == 0) ? 0.0f : __expf(fmaf(beta, sv.y, acc[i][1] * scale));
        o.z = (m4.z == 0) ? 0.0f : __expf(fmaf(beta, sv.z, acc[i][2] * scale));
        o.w = (m4.w == 0) ? 0.0f : __expf(fmaf(beta, sv.w, acc[i][3] * scale));
        *(float4*)(attn + ((size_t)bh * Sc + q) * Sc + kcol) = o;
        rsum[i] = (o.x + o.y) + (o.z + o.w);
    }

    // Block-level row reduction, then one atomic per row.
    #pragma unroll
    for (int i = 0; i < 4; i++) red[ty * 4 + i][tx] = rsum[i];
    __syncthreads();
    if (tid < BQ) {
        float s = 0.0f;
        #pragma unroll
        for (int j = 0; j < 16; j++) s += red[tid][j];
        atomicAdd(&g_rowsum[(size_t)bh * Sc + q0 + tid], s);
    }
}

// ---------------------------------------------------------------------------
// Fused normalize + AV:
//   reads exp-scores from attn, w = e * (1/rowsum), writes w back (final
//   attention_weights output) and accumulates ctx = w @ V.
// 128 (q) x 64 (d) tile per block, k-chunks of 32, 8x4 per thread.
// ---------------------------------------------------------------------------
__global__ __launch_bounds__(256) void av_norm_kernel(float* __restrict__ attn)
{
    const float* V = g_buf + 2 * CHUNK;
    float*     ctx = g_buf + 3 * CHUNK;

    constexpr int BQ = 128, BKk = 32;
    __shared__ float As[BKk][BQ + 4];
    __shared__ float Vs[BKk][HDc + 4];
    __shared__ float inv[BQ];

    const int bh = blockIdx.z, b = bh >> 4, h = bh & 15;
    const int q0 = blockIdx.x * BQ;
    const int tid = threadIdx.x, tx = tid & 15, ty = tid >> 4;

    if (tid < BQ) inv[tid] = 1.0f / g_rowsum[(size_t)bh * Sc + q0 + tid];
    __syncthreads();

    float* Abase = attn + ((size_t)bh * Sc + q0) * Sc;
    const float* Vbase = V + (size_t)b * Sc * HIDc + h * HDc;

    float acc[8][4];
    #pragma unroll
    for (int i = 0; i < 8; i++)
        #pragma unroll
        for (int j = 0; j < 4; j++) acc[i][j] = 0.0f;

    for (int k0 = 0; k0 < Sc; k0 += BKk) {
        // exp tile: 128 rows x 32 cols, normalize, stash to smem + write back.
        #pragma unroll
        for (int L = 0; L < 4; L++) {
            const int e  = tid + L * 256;
            const int ar = e >> 3, ac = (e & 7) * 4;
            float* gp = Abase + (size_t)ar * Sc + k0 + ac;
            float4 av = *(const float4*)gp;
            const float iv = inv[ar];
            av.x *= iv; av.y *= iv; av.z *= iv; av.w *= iv;
            As[ac + 0][ar] = av.x; As[ac + 1][ar] = av.y;
            As[ac + 2][ar] = av.z; As[ac + 3][ar] = av.w;
            *(float4*)gp = av;   // final attention weights
        }
        // V tile: 32 rows x 64 cols.
        #pragma unroll
        for (int L = 0; L < 2; L++) {
            const int e  = tid + L * 256;
            const int vr = e >> 4, vc = (e & 15) * 4;
            *(float4*)&Vs[vr][vc] =
                *(const float4*)(Vbase + (size_t)(k0 + vr) * HIDc + vc);
        }
        __syncthreads();
        #pragma unroll
        for (int kk = 0; kk < BKk; kk++) {
            float a[8], v[4];
            *(float4*)&a[0] = *(const float4*)&As[kk][ty * 8];
            *(float4*)&a[4] = *(const float4*)&As[kk][ty * 8 + 4];
            *(float4*)&v[0] = *(const float4*)&Vs[kk][tx * 4];
            #pragma unroll
            for (int i = 0; i < 8; i++)
                #pragma unroll
                for (int j = 0; j < 4; j++)
                    acc[i][j] = fmaf(a[i], v[j], acc[i][j]);
        }
        __syncthreads();
    }

    #pragma unroll
    for (int i = 0; i < 8; i++) {
        const int q = q0 + ty * 8 + i;
        float4 o = make_float4(acc[i][0], acc[i][1], acc[i][2], acc[i][3]);
        *(float4*)(ctx + ((size_t)b * Sc + q) * HIDc + h * HDc + tx * 4) = o;
    }
}

// ---------------------------------------------------------------------------
// Launcher
// ---------------------------------------------------------------------------
extern "C" void kernel_launch(void* const* d_in, const int* in_sizes, int n_in,
                              void* d_out, int out_size)
{
    const float* query = (const float*)d_in[0];
    const float* key   = (const float*)d_in[1];
    const float* value = (const float*)d_in[2];
    const int*   amask = (const int*)  d_in[3];
    const float* sim   = (const float*)d_in[4];
    const float* Wq    = (const float*)d_in[5];
    const float* bq    = (const float*)d_in[6];
    const float* Wk    = (const float*)d_in[7];
    const float* bk    = (const float*)d_in[8];
    const float* Wv    = (const float*)d_in[9];
    const float* bv    = (const float*)d_in[10];
    const float* Wo    = (const float*)d_in[11];
    const float* bo    = (const float*)d_in[12];
    const float* beta  = (const float*)d_in[13];

    float* out  = (float*)d_out;
    float* attn = out + CHUNK;   // attention_weights region [B,NH,S,S]

    zero_rowsum_kernel<<<NROWS / (256 * 4), 256>>>();

    dim3 gp(HIDc / 64, Mtot / 128);                   // (16, 32) = 512 blocks
    sgemm_nt_bias<<<gp, 256>>>(query, -1, Wq, bq, nullptr, 0, Mtot, HIDc, HIDc);
    sgemm_nt_bias<<<gp, 256>>>(key,   -1, Wk, bk, nullptr, 1, Mtot, HIDc, HIDc);
    sgemm_nt_bias<<<gp, 256>>>(value, -1, Wv, bv, nullptr, 2, Mtot, HIDc, HIDc);

    dim3 gs(Sc / 64, Sc / 64, Bc * NHc);              // (32, 32, 32)
    scores_exp_kernel<<<gs, 256>>>(sim, amask, beta, attn);

    dim3 ga(Sc / 128, 1, Bc * NHc);                   // (16, 1, 32)
    av_norm_kernel<<<ga, 256>>>(attn);

    sgemm_nt_bias<<<gp, 256>>>(nullptr, 3, Wo, bo, out, -1, Mtot, HIDc, HIDc);
}

// round 8
// speedup vs baseline: 1.2321x; 1.2321x over previous
#include <cuda_runtime.h>
#include <cuda_bf16.h>
#include <cstdint>

// Problem constants
constexpr int Bc   = 2;
constexpr int Sc   = 2048;
constexpr int HIDc = 1024;
constexpr int NHc  = 16;
constexpr int HDc  = 64;           // HID / NH
constexpr int Mtot = Bc * Sc;      // 4096
constexpr size_t CHUNK = (size_t)Bc * Sc * HIDc;  // 4,194,304 floats
constexpr size_t WSZ   = (size_t)HIDc * HIDc;     // 1,048,576
constexpr int NROWS = Bc * NHc * Sc;              // 65536 softmax rows

// fp32 scratch: [0]=Q, [1]=K, [2]=V, [3]=ctx
__device__ float g_buf[4 * CHUNK];
__device__ float g_rowsum[NROWS];
// bf16 split-precision scratch
__device__ __nv_bfloat16 g_inh[3 * CHUNK];   // query,key,value hi
__device__ __nv_bfloat16 g_inl[3 * CHUNK];   // lo
__device__ __nv_bfloat16 g_wh[4 * WSZ];      // Wq,Wk,Wv,Wo hi
__device__ __nv_bfloat16 g_wl[4 * WSZ];      // lo
__device__ __nv_bfloat16 g_ch[CHUNK];        // ctx hi
__device__ __nv_bfloat16 g_cl[CHUNK];        // ctx lo

__device__ __forceinline__ uint32_t smem_u32(const void* p) {
    uint32_t a;
    asm("{ .reg .u64 t; cvta.to.shared.u64 t, %1; cvt.u32.u64 %0, t; }"
        : "=r"(a) : "l"(p));
    return a;
}

#define LDSM4(r, addr) \
    asm volatile("ldmatrix.sync.aligned.m8n8.x4.shared.b16 {%0,%1,%2,%3}, [%4];" \
        : "=r"((r)[0]), "=r"((r)[1]), "=r"((r)[2]), "=r"((r)[3]) : "r"(addr))
#define LDSM2(r, addr) \
    asm volatile("ldmatrix.sync.aligned.m8n8.x2.shared.b16 {%0,%1}, [%2];" \
        : "=r"((r)[0]), "=r"((r)[1]) : "r"(addr))
#define MMA16816(c, a, b) \
    asm volatile("mma.sync.aligned.m16n8k16.row.col.f32.bf16.bf16.f32 " \
        "{%0,%1,%2,%3}, {%4,%5,%6,%7}, {%8,%9}, {%0,%1,%2,%3};" \
        : "+f"((c)[0]), "+f"((c)[1]), "+f"((c)[2]), "+f"((c)[3]) \
        : "r"((a)[0]), "r"((a)[1]), "r"((a)[2]), "r"((a)[3]), \
          "r"((b)[0]), "r"((b)[1]))

// ---------------------------------------------------------------------------
// Zero the rowsum accumulator.
// ---------------------------------------------------------------------------
__global__ void zero_rowsum_kernel()
{
    const int i = blockIdx.x * blockDim.x + threadIdx.x;
    ((float4*)g_rowsum)[i] = make_float4(0.f, 0.f, 0.f, 0.f);
}

// ---------------------------------------------------------------------------
// Split fp32 -> (bf16 hi, bf16 lo). src_sel: -1 ext, 0..3 g_buf chunk.
// dst_sel: 0..2 -> g_inh/inl + sel*CHUNK; 3 -> g_ch/g_cl; 4..7 -> weights.
// ---------------------------------------------------------------------------
__global__ __launch_bounds__(256) void convert_split(
    const float* __restrict__ srcExt, int src_sel, int dst_sel)
{
    const float* src = (src_sel >= 0) ? g_buf + (size_t)src_sel * CHUNK : srcExt;
    __nv_bfloat16 *h, *l;
    if (dst_sel < 3)      { h = g_inh + (size_t)dst_sel * CHUNK; l = g_inl + (size_t)dst_sel * CHUNK; }
    else if (dst_sel == 3){ h = g_ch; l = g_cl; }
    else                  { h = g_wh + (size_t)(dst_sel - 4) * WSZ; l = g_wl + (size_t)(dst_sel - 4) * WSZ; }

    const size_t i = ((size_t)blockIdx.x * 256 + threadIdx.x) * 4;
    float4 x = *(const float4*)(src + i);
    __nv_bfloat16 h0 = __float2bfloat16(x.x), h1 = __float2bfloat16(x.y);
    __nv_bfloat16 h2 = __float2bfloat16(x.z), h3 = __float2bfloat16(x.w);
    __nv_bfloat16 l0 = __float2bfloat16(x.x - __bfloat162float(h0));
    __nv_bfloat16 l1 = __float2bfloat16(x.y - __bfloat162float(h1));
    __nv_bfloat16 l2 = __float2bfloat16(x.z - __bfloat162float(h2));
    __nv_bfloat16 l3 = __float2bfloat16(x.w - __bfloat162float(h3));
    __nv_bfloat162 hp0(h0, h1), hp1(h2, h3), lp0(l0, l1), lp1(l2, l3);
    uint2 hv, lv;
    hv.x = *(uint32_t*)&hp0; hv.y = *(uint32_t*)&hp1;
    lv.x = *(uint32_t*)&lp0; lv.y = *(uint32_t*)&lp1;
    *(uint2*)(h + i) = hv;
    *(uint2*)(l + i) = lv;
}

// ---------------------------------------------------------------------------
// mma.sync bf16 split GEMM: C[m,n] = sum_k A[m,k]*W[n,k] + bias[n]
// Block tile 128x128, BK=32, 8 warps in 2(m) x 4(n), warp tile 64x32.
// 3-way split: Ah*Wh + Ah*Wl + Al*Wh, fp32 accumulators.
// ---------------------------------------------------------------------------
__global__ __launch_bounds__(256) void gemm_bf16x3(
    int a_sel, int w_sel, const float* __restrict__ bias,
    float* __restrict__ Cext, int c_sel)
{
    const __nv_bfloat16* Ah = (a_sel < 3) ? g_inh + (size_t)a_sel * CHUNK : g_ch;
    const __nv_bfloat16* Al = (a_sel < 3) ? g_inl + (size_t)a_sel * CHUNK : g_cl;
    const __nv_bfloat16* Wh = g_wh + (size_t)w_sel * WSZ;
    const __nv_bfloat16* Wl = g_wl + (size_t)w_sel * WSZ;
    float* C = (c_sel >= 0) ? g_buf + (size_t)c_sel * CHUNK : Cext;

    constexpr int LDT = 40;   // smem row stride (bf16): 80B -> conflict-free ldmatrix
    __shared__ __nv_bfloat16 sAh[128 * LDT];
    __shared__ __nv_bfloat16 sAl[128 * LDT];
    __shared__ __nv_bfloat16 sBh[128 * LDT];
    __shared__ __nv_bfloat16 sBl[128 * LDT];

    const int tid = threadIdx.x, wid = tid >> 5, lane = tid & 31;
    const int m0 = blockIdx.y * 128, n0 = blockIdx.x * 128;
    const int wm = wid >> 2, wn = wid & 3;

    const uint32_t aAh = smem_u32(sAh), aAl = smem_u32(sAl);
    const uint32_t aBh = smem_u32(sBh), aBl = smem_u32(sBl);

    float acc[4][4][4];
    #pragma unroll
    for (int i = 0; i < 4; i++)
        #pragma unroll
        for (int j = 0; j < 4; j++)
            #pragma unroll
            for (int t = 0; t < 4; t++) acc[i][j][t] = 0.0f;

    // Per-thread smem load coords: 2 uint4 per tile per thread.
    const int r0 = tid >> 2, c0v = (tid & 3) * 8;           // e = tid
    const int r1 = (tid + 256) >> 2, c1v = c0v;             // e = tid + 256

    // ldmatrix per-thread addresses (byte offsets added per use).
    const uint32_t aoff = ((lane & 15) * LDT + (lane >> 4) * 8) * 2;
    const uint32_t boff = ((lane & 7) * LDT + ((lane >> 3) & 1) * 8) * 2;

    for (int kc = 0; kc < 32; kc++) {
        const int kb = kc * 32;
        {
            const size_t gA0 = (size_t)(m0 + r0) * HIDc + kb + c0v;
            const size_t gA1 = (size_t)(m0 + r1) * HIDc + kb + c1v;
            const size_t gB0 = (size_t)(n0 + r0) * HIDc + kb + c0v;
            const size_t gB1 = (size_t)(n0 + r1) * HIDc + kb + c1v;
            *(uint4*)&sAh[r0 * LDT + c0v] = *(const uint4*)(Ah + gA0);
            *(uint4*)&sAh[r1 * LDT + c1v] = *(const uint4*)(Ah + gA1);
            *(uint4*)&sAl[r0 * LDT + c0v] = *(const uint4*)(Al + gA0);
            *(uint4*)&sAl[r1 * LDT + c1v] = *(const uint4*)(Al + gA1);
            *(uint4*)&sBh[r0 * LDT + c0v] = *(const uint4*)(Wh + gB0);
            *(uint4*)&sBh[r1 * LDT + c1v] = *(const uint4*)(Wh + gB1);
            *(uint4*)&sBl[r0 * LDT + c0v] = *(const uint4*)(Wl + gB0);
            *(uint4*)&sBl[r1 * LDT + c1v] = *(const uint4*)(Wl + gB1);
        }
        __syncthreads();

        #pragma unroll
        for (int ks = 0; ks < 32; ks += 16) {
            uint32_t af[4][4], bh[4][2], bl[4][2];
            // Ah fragments
            #pragma unroll
            for (int i = 0; i < 4; i++)
                LDSM4(af[i], aAh + ((wm * 64 + i * 16) * LDT + ks) * 2 + aoff);
            // Wh fragments
            #pragma unroll
            for (int j = 0; j < 4; j++)
                LDSM2(bh[j], aBh + ((wn * 32 + j * 8) * LDT + ks) * 2 + boff);
            #pragma unroll
            for (int i = 0; i < 4; i++)
                #pragma unroll
                for (int j = 0; j < 4; j++) MMA16816(acc[i][j], af[i], bh[j]);
            // Wl fragments
            #pragma unroll
            for (int j = 0; j < 4; j++)
                LDSM2(bl[j], aBl + ((wn * 32 + j * 8) * LDT + ks) * 2 + boff);
            #pragma unroll
            for (int i = 0; i < 4; i++)
                #pragma unroll
                for (int j = 0; j < 4; j++) MMA16816(acc[i][j], af[i], bl[j]);
            // Al fragments (reuse af regs)
            #pragma unroll
            for (int i = 0; i < 4; i++)
                LDSM4(af[i], aAl + ((wm * 64 + i * 16) * LDT + ks) * 2 + aoff);
            #pragma unroll
            for (int i = 0; i < 4; i++)
                #pragma unroll
                for (int j = 0; j < 4; j++) MMA16816(acc[i][j], af[i], bh[j]);
        }
        __syncthreads();
    }

    // Epilogue: thread t of warp holds rows (t/4, t/4+8), cols (t%4)*2, +1
    const int er = lane >> 2, ec = (lane & 3) * 2;
    #pragma unroll
    for (int j = 0; j < 4; j++) {
        const int n = n0 + wn * 32 + j * 8 + ec;
        const float bx = bias[n], by = bias[n + 1];
        #pragma unroll
        for (int i = 0; i < 4; i++) {
            const int m = m0 + wm * 64 + i * 16 + er;
            float2 lo = make_float2(acc[i][j][0] + bx, acc[i][j][1] + by);
            float2 hi = make_float2(acc[i][j][2] + bx, acc[i][j][3] + by);
            *(float2*)(C + (size_t)m * HIDc + n) = lo;
            *(float2*)(C + (size_t)(m + 8) * HIDc + n) = hi;
        }
    }
}

// ---------------------------------------------------------------------------
// Scores+exp (fp32): attn = exp((Q.K)/8 + beta*sim), masked -> 0.
// 64x64 tile, 4x4 per thread; per-row exp sums -> g_rowsum atomics.
// ---------------------------------------------------------------------------
__global__ __launch_bounds__(256) void scores_exp_kernel(
    const float* __restrict__ sim, const int* __restrict__ amask,
    const float* __restrict__ beta_p, float* __restrict__ attn)
{
    const float* Q  = g_buf;
    const float* Kh = g_buf + CHUNK;

    constexpr int BQ = 64, BKt = 64, BD = 16;
    __shared__ float Qs[BD][BQ + 4];
    __shared__ float Ks[BD][BKt + 4];
    __shared__ float red[BQ][17];

    const int bh = blockIdx.z, b = bh >> 4, h = bh & 15;
    const int q0 = blockIdx.y * BQ, k0 = blockIdx.x * BKt;
    const int tid = threadIdx.x, tx = tid & 15, ty = tid >> 4;

    const int lrow = tid >> 2;
    const int lcol = (tid & 3) * 4;
    const size_t qbase = ((size_t)b * Sc + q0 + lrow) * HIDc + h * HDc + lcol;
    const size_t kbase = ((size_t)b * Sc + k0 + lrow) * HIDc + h * HDc + lcol;

    float acc[4][4] = {};

    #pragma unroll
    for (int d0 = 0; d0 < HDc; d0 += BD) {
        float4 qv = *(const float4*)(Q + qbase + d0);
        float4 kv = *(const float4*)(Kh + kbase + d0);
        Qs[lcol + 0][lrow] = qv.x; Qs[lcol + 1][lrow] = qv.y;
        Qs[lcol + 2][lrow] = qv.z; Qs[lcol + 3][lrow] = qv.w;
        Ks[lcol + 0][lrow] = kv.x; Ks[lcol + 1][lrow] = kv.y;
        Ks[lcol + 2][lrow] = kv.z; Ks[lcol + 3][lrow] = kv.w;
        __syncthreads();
        #pragma unroll
        for (int kk = 0; kk < BD; kk++) {
            float a[4], c[4];
            *(float4*)a = *(const float4*)&Qs[kk][ty * 4];
            *(float4*)c = *(const float4*)&Ks[kk][tx * 4];
            #pragma unroll
            for (int i = 0; i < 4; i++)
                #pragma unroll
                for (int j = 0; j < 4; j++)
                    acc[i][j] = fmaf(a[i], c[j], acc[i][j]);
        }
        __syncthreads();
    }

    const float beta = *beta_p;
    const float scale = 0.125f;
    const int kcol = k0 + tx * 4;
    const int4 m4 = *(const int4*)(amask + (size_t)b * Sc + kcol);

    float rsum[4];
    #pragma unroll
    for (int i = 0; i < 4; i++) {
        const int q = q0 + ty * 4 + i;
        const float4 sv = *(const float4*)(sim + ((size_t)b * Sc + q) * Sc + kcol);
        float4 o;
        o.x = (m4.x == 0) ? 0.0f : __expf(fmaf(beta, sv.x, acc[i][0] * scale));
        o.y = (m4.y == 0) ? 0.0f : __expf(fmaf(beta, sv.y, acc[i][1] * scale));
        o.z = (m4.z == 0) ? 0.0f : __expf(fmaf(beta, sv.z, acc[i][2] * scale));
        o.w = (m4.w == 0) ? 0.0f : __expf(fmaf(beta, sv.w, acc[i][3] * scale));
        *(float4*)(attn + ((size_t)bh * Sc + q) * Sc + kcol) = o;
        rsum[i] = (o.x + o.y) + (o.z + o.w);
    }

    #pragma unroll
    for (int i = 0; i < 4; i++) red[ty * 4 + i][tx] = rsum[i];
    __syncthreads();
    if (tid < BQ) {
        float s = 0.0f;
        #pragma unroll
        for (int j = 0; j < 16; j++) s += red[tid][j];
        atomicAdd(&g_rowsum[(size_t)bh * Sc + q0 + tid], s);
    }
}

// ---------------------------------------------------------------------------
// Fused normalize + AV.
// ---------------------------------------------------------------------------
__global__ __launch_bounds__(256) void av_norm_kernel(float* __restrict__ attn)
{
    const float* V = g_buf + 2 * CHUNK;
    float*     ctx = g_buf + 3 * CHUNK;

    constexpr int BQ = 128, BKk = 32;
    __shared__ float As[BKk][BQ + 4];
    __shared__ float Vs[BKk][HDc + 4];
    __shared__ float inv[BQ];

    const int bh = blockIdx.z, b = bh >> 4, h = bh & 15;
    const int q0 = blockIdx.x * BQ;
    const int tid = threadIdx.x, tx = tid & 15, ty = tid >> 4;

    if (tid < BQ) inv[tid] = 1.0f / g_rowsum[(size_t)bh * Sc + q0 + tid];
    __syncthreads();

    float* Abase = attn + ((size_t)bh * Sc + q0) * Sc;
    const float* Vbase = V + (size_t)b * Sc * HIDc + h * HDc;

    float acc[8][4];
    #pragma unroll
    for (int i = 0; i < 8; i++)
        #pragma unroll
        for (int j = 0; j < 4; j++) acc[i][j] = 0.0f;

    for (int k0 = 0; k0 < Sc; k0 += BKk) {
        #pragma unroll
        for (int L = 0; L < 4; L++) {
            const int e  = tid + L * 256;
            const int ar = e >> 3, ac = (e & 7) * 4;
            float* gp = Abase + (size_t)ar * Sc + k0 + ac;
            float4 av = *(const float4*)gp;
            const float iv = inv[ar];
            av.x *= iv; av.y *= iv; av.z *= iv; av.w *= iv;
            As[ac + 0][ar] = av.x; As[ac + 1][ar] = av.y;
            As[ac + 2][ar] = av.z; As[ac + 3][ar] = av.w;
            *(float4*)gp = av;
        }
        #pragma unroll
        for (int L = 0; L < 2; L++) {
            const int e  = tid + L * 256;
            const int vr = e >> 4, vc = (e & 15) * 4;
            *(float4*)&Vs[vr][vc] =
                *(const float4*)(Vbase + (size_t)(k0 + vr) * HIDc + vc);
        }
        __syncthreads();
        #pragma unroll
        for (int kk = 0; kk < BKk; kk++) {
            float a[8], v[4];
            *(float4*)&a[0] = *(const float4*)&As[kk][ty * 8];
            *(float4*)&a[4] = *(const float4*)&As[kk][ty * 8 + 4];
            *(float4*)&v[0] = *(const float4*)&Vs[kk][tx * 4];
            #pragma unroll
            for (int i = 0; i < 8; i++)
                #pragma unroll
                for (int j = 0; j < 4; j++)
                    acc[i][j] = fmaf(a[i], v[j], acc[i][j]);
        }
        __syncthreads();
    }

    #pragma unroll
    for (int i = 0; i < 8; i++) {
        const int q = q0 + ty * 8 + i;
        float4 o = make_float4(acc[i][0], acc[i][1], acc[i][2], acc[i][3]);
        *(float4*)(ctx + ((size_t)b * Sc + q) * HIDc + h * HDc + tx * 4) = o;
    }
}

// ---------------------------------------------------------------------------
// Launcher
// ---------------------------------------------------------------------------
extern "C" void kernel_launch(void* const* d_in, const int* in_sizes, int n_in,
                              void* d_out, int out_size)
{
    const float* query = (const float*)d_in[0];
    const float* key   = (const float*)d_in[1];
    const float* value = (const float*)d_in[2];
    const int*   amask = (const int*)  d_in[3];
    const float* sim   = (const float*)d_in[4];
    const float* Wq    = (const float*)d_in[5];
    const float* bq    = (const float*)d_in[6];
    const float* Wk    = (const float*)d_in[7];
    const float* bk    = (const float*)d_in[8];
    const float* Wv    = (const float*)d_in[9];
    const float* bv    = (const float*)d_in[10];
    const float* Wo    = (const float*)d_in[11];
    const float* bo    = (const float*)d_in[12];
    const float* beta  = (const float*)d_in[13];

    float* out  = (float*)d_out;
    float* attn = out + CHUNK;   // attention_weights region [B,NH,S,S]

    zero_rowsum_kernel<<<NROWS / (256 * 4), 256>>>();

    // Split-precision conversions.
    const int cgrid = (int)(CHUNK / 1024);   // 4096 blocks (4 floats/thread)
    const int wgrid = (int)(WSZ / 1024);     // 1024 blocks
    convert_split<<<cgrid, 256>>>(query, -1, 0);
    convert_split<<<cgrid, 256>>>(key,   -1, 1);
    convert_split<<<cgrid, 256>>>(value, -1, 2);
    convert_split<<<wgrid, 256>>>(Wq, -1, 4);
    convert_split<<<wgrid, 256>>>(Wk, -1, 5);
    convert_split<<<wgrid, 256>>>(Wv, -1, 6);
    convert_split<<<wgrid, 256>>>(Wo, -1, 7);

    // Projections on tensor cores (3x bf16 split, mma.sync path).
    dim3 gg(HIDc / 128, Mtot / 128);          // (8, 32)
    gemm_bf16x3<<<gg, 256>>>(0, 0, bq, nullptr, 0);
    gemm_bf16x3<<<gg, 256>>>(1, 1, bk, nullptr, 1);
    gemm_bf16x3<<<gg, 256>>>(2, 2, bv, nullptr, 2);

    dim3 gs(Sc / 64, Sc / 64, Bc * NHc);      // (32, 32, 32)
    scores_exp_kernel<<<gs, 256>>>(sim, amask, beta, attn);

    dim3 ga(Sc / 128, 1, Bc * NHc);           // (16, 1, 32)
    av_norm_kernel<<<ga, 256>>>(attn);

    // Output projection.
    convert_split<<<cgrid, 256>>>(nullptr, 3, 3);
    gemm_bf16x3<<<gg, 256>>>(3, 3, bo, out, -1);
}

// round 9
// speedup vs baseline: 1.5495x; 1.2576x over previous
#include <cuda_runtime.h>
#include <cuda_bf16.h>
#include <cstdint>

// Problem constants
constexpr int Bc   = 2;
constexpr int Sc   = 2048;
constexpr int HIDc = 1024;
constexpr int NHc  = 16;
constexpr int HDc  = 64;           // HID / NH
constexpr int Mtot = Bc * Sc;      // 4096
constexpr size_t CHUNK = (size_t)Bc * Sc * HIDc;  // 4,194,304 floats
constexpr size_t WSZ   = (size_t)HIDc * HIDc;     // 1,048,576
constexpr int NROWS = Bc * NHc * Sc;              // 65536 softmax rows

__device__ float g_rowsum[NROWS];
// bf16 split-precision scratch
__device__ __nv_bfloat16 g_inh[3 * CHUNK];   // query,key,value inputs hi
__device__ __nv_bfloat16 g_inl[3 * CHUNK];   // lo
__device__ __nv_bfloat16 g_wh[4 * WSZ];      // Wq,Wk,Wv,Wo hi
__device__ __nv_bfloat16 g_wl[4 * WSZ];      // lo
__device__ __nv_bfloat16 g_qkvh[3 * CHUNK];  // projected Q,K,V hi
__device__ __nv_bfloat16 g_qkvl[3 * CHUNK];  // lo
__device__ __nv_bfloat16 g_ch[CHUNK];        // ctx hi
__device__ __nv_bfloat16 g_cl[CHUNK];        // ctx lo

__device__ __forceinline__ uint32_t smem_u32(const void* p) {
    uint32_t a;
    asm("{ .reg .u64 t; cvta.to.shared.u64 t, %1; cvt.u32.u64 %0, t; }"
        : "=r"(a) : "l"(p));
    return a;
}

#define LDSM4(r, addr) \
    asm volatile("ldmatrix.sync.aligned.m8n8.x4.shared.b16 {%0,%1,%2,%3}, [%4];" \
        : "=r"((r)[0]), "=r"((r)[1]), "=r"((r)[2]), "=r"((r)[3]) : "r"(addr))
#define LDSM2(r, addr) \
    asm volatile("ldmatrix.sync.aligned.m8n8.x2.shared.b16 {%0,%1}, [%2];" \
        : "=r"((r)[0]), "=r"((r)[1]) : "r"(addr))
#define LDSM2T(r, addr) \
    asm volatile("ldmatrix.sync.aligned.m8n8.x2.trans.shared.b16 {%0,%1}, [%2];" \
        : "=r"((r)[0]), "=r"((r)[1]) : "r"(addr))
#define MMA16816(c, a, b) \
    asm volatile("mma.sync.aligned.m16n8k16.row.col.f32.bf16.bf16.f32 " \
        "{%0,%1,%2,%3}, {%4,%5,%6,%7}, {%8,%9}, {%0,%1,%2,%3};" \
        : "+f"((c)[0]), "+f"((c)[1]), "+f"((c)[2]), "+f"((c)[3]) \
        : "r"((a)[0]), "r"((a)[1]), "r"((a)[2]), "r"((a)[3]), \
          "r"((b)[0]), "r"((b)[1]))

__device__ __forceinline__ void split2(float x, __nv_bfloat16& h, __nv_bfloat16& l) {
    h = __float2bfloat16(x);
    l = __float2bfloat16(x - __bfloat162float(h));
}

// ---------------------------------------------------------------------------
// Zero the rowsum accumulator.
// ---------------------------------------------------------------------------
__global__ void zero_rowsum_kernel()
{
    const int i = blockIdx.x * blockDim.x + threadIdx.x;
    ((float4*)g_rowsum)[i] = make_float4(0.f, 0.f, 0.f, 0.f);
}

// ---------------------------------------------------------------------------
// Split fp32 -> (bf16 hi, bf16 lo). dst_sel: 0..2 inputs, 4..7 weights.
// ---------------------------------------------------------------------------
__global__ __launch_bounds__(256) void convert_split(
    const float* __restrict__ src, int dst_sel)
{
    __nv_bfloat16 *h, *l;
    if (dst_sel < 3) { h = g_inh + (size_t)dst_sel * CHUNK; l = g_inl + (size_t)dst_sel * CHUNK; }
    else             { h = g_wh + (size_t)(dst_sel - 4) * WSZ; l = g_wl + (size_t)(dst_sel - 4) * WSZ; }

    const size_t i = ((size_t)blockIdx.x * 256 + threadIdx.x) * 4;
    float4 x = *(const float4*)(src + i);
    __nv_bfloat16 h0, h1, h2, h3, l0, l1, l2, l3;
    split2(x.x, h0, l0); split2(x.y, h1, l1);
    split2(x.z, h2, l2); split2(x.w, h3, l3);
    __nv_bfloat162 hp0(h0, h1), hp1(h2, h3), lp0(l0, l1), lp1(l2, l3);
    uint2 hv, lv;
    hv.x = *(uint32_t*)&hp0; hv.y = *(uint32_t*)&hp1;
    lv.x = *(uint32_t*)&lp0; lv.y = *(uint32_t*)&lp1;
    *(uint2*)(h + i) = hv;
    *(uint2*)(l + i) = lv;
}

// ---------------------------------------------------------------------------
// mma.sync bf16 split GEMM: C[m,n] = sum_k A[m,k]*W[n,k] + bias[n]
// Block tile 128x128, BK=32, 8 warps 2(m) x 4(n), warp tile 64x32.
// a_sel: 0..2 = g_inh/inl; 3 = ctx (g_ch/g_cl).
// osel < 0: fp32 out to Cext. osel >= 0: split bf16 out to g_qkvh/l[osel].
// ---------------------------------------------------------------------------
__global__ __launch_bounds__(256) void gemm_bf16x3(
    int a_sel, int w_sel, const float* __restrict__ bias,
    float* __restrict__ Cext, int osel)
{
    const __nv_bfloat16* Ah = (a_sel < 3) ? g_inh + (size_t)a_sel * CHUNK : g_ch;
    const __nv_bfloat16* Al = (a_sel < 3) ? g_inl + (size_t)a_sel * CHUNK : g_cl;
    const __nv_bfloat16* Wh = g_wh + (size_t)w_sel * WSZ;
    const __nv_bfloat16* Wl = g_wl + (size_t)w_sel * WSZ;

    constexpr int LDT = 40;
    __shared__ __nv_bfloat16 sAh[128 * LDT];
    __shared__ __nv_bfloat16 sAl[128 * LDT];
    __shared__ __nv_bfloat16 sBh[128 * LDT];
    __shared__ __nv_bfloat16 sBl[128 * LDT];

    const int tid = threadIdx.x, wid = tid >> 5, lane = tid & 31;
    const int m0 = blockIdx.y * 128, n0 = blockIdx.x * 128;
    const int wm = wid >> 2, wn = wid & 3;

    const uint32_t aAh = smem_u32(sAh), aAl = smem_u32(sAl);
    const uint32_t aBh = smem_u32(sBh), aBl = smem_u32(sBl);

    float acc[4][4][4];
    #pragma unroll
    for (int i = 0; i < 4; i++)
        #pragma unroll
        for (int j = 0; j < 4; j++)
            #pragma unroll
            for (int t = 0; t < 4; t++) acc[i][j][t] = 0.0f;

    const int r0 = tid >> 2, c0v = (tid & 3) * 8;
    const int r1 = (tid + 256) >> 2;

    const uint32_t aoff = ((lane & 15) * LDT + (lane >> 4) * 8) * 2;
    const uint32_t boff = ((lane & 7) * LDT + ((lane >> 3) & 1) * 8) * 2;

    for (int kc = 0; kc < 32; kc++) {
        const int kb = kc * 32;
        {
            const size_t gA0 = (size_t)(m0 + r0) * HIDc + kb + c0v;
            const size_t gA1 = (size_t)(m0 + r1) * HIDc + kb + c0v;
            const size_t gB0 = (size_t)(n0 + r0) * HIDc + kb + c0v;
            const size_t gB1 = (size_t)(n0 + r1) * HIDc + kb + c0v;
            *(uint4*)&sAh[r0 * LDT + c0v] = *(const uint4*)(Ah + gA0);
            *(uint4*)&sAh[r1 * LDT + c0v] = *(const uint4*)(Ah + gA1);
            *(uint4*)&sAl[r0 * LDT + c0v] = *(const uint4*)(Al + gA0);
            *(uint4*)&sAl[r1 * LDT + c0v] = *(const uint4*)(Al + gA1);
            *(uint4*)&sBh[r0 * LDT + c0v] = *(const uint4*)(Wh + gB0);
            *(uint4*)&sBh[r1 * LDT + c0v] = *(const uint4*)(Wh + gB1);
            *(uint4*)&sBl[r0 * LDT + c0v] = *(const uint4*)(Wl + gB0);
            *(uint4*)&sBl[r1 * LDT + c0v] = *(const uint4*)(Wl + gB1);
        }
        __syncthreads();

        #pragma unroll
        for (int ks = 0; ks < 32; ks += 16) {
            uint32_t af[4][4], bh[4][2], bl[4][2];
            #pragma unroll
            for (int i = 0; i < 4; i++)
                LDSM4(af[i], aAh + ((wm * 64 + i * 16) * LDT + ks) * 2 + aoff);
            #pragma unroll
            for (int j = 0; j < 4; j++)
                LDSM2(bh[j], aBh + ((wn * 32 + j * 8) * LDT + ks) * 2 + boff);
            #pragma unroll
            for (int i = 0; i < 4; i++)
                #pragma unroll
                for (int j = 0; j < 4; j++) MMA16816(acc[i][j], af[i], bh[j]);
            #pragma unroll
            for (int j = 0; j < 4; j++)
                LDSM2(bl[j], aBl + ((wn * 32 + j * 8) * LDT + ks) * 2 + boff);
            #pragma unroll
            for (int i = 0; i < 4; i++)
                #pragma unroll
                for (int j = 0; j < 4; j++) MMA16816(acc[i][j], af[i], bl[j]);
            #pragma unroll
            for (int i = 0; i < 4; i++)
                LDSM4(af[i], aAl + ((wm * 64 + i * 16) * LDT + ks) * 2 + aoff);
            #pragma unroll
            for (int i = 0; i < 4; i++)
                #pragma unroll
                for (int j = 0; j < 4; j++) MMA16816(acc[i][j], af[i], bh[j]);
        }
        __syncthreads();
    }

    const int er = lane >> 2, ec = (lane & 3) * 2;
    if (osel < 0) {
        #pragma unroll
        for (int j = 0; j < 4; j++) {
            const int n = n0 + wn * 32 + j * 8 + ec;
            const float bx = bias[n], by = bias[n + 1];
            #pragma unroll
            for (int i = 0; i < 4; i++) {
                const int m = m0 + wm * 64 + i * 16 + er;
                *(float2*)(Cext + (size_t)m * HIDc + n) =
                    make_float2(acc[i][j][0] + bx, acc[i][j][1] + by);
                *(float2*)(Cext + (size_t)(m + 8) * HIDc + n) =
                    make_float2(acc[i][j][2] + bx, acc[i][j][3] + by);
            }
        }
    } else {
        __nv_bfloat16* dh = g_qkvh + (size_t)osel * CHUNK;
        __nv_bfloat16* dl = g_qkvl + (size_t)osel * CHUNK;
        #pragma unroll
        for (int j = 0; j < 4; j++) {
            const int n = n0 + wn * 32 + j * 8 + ec;
            const float bx = bias[n], by = bias[n + 1];
            #pragma unroll
            for (int i = 0; i < 4; i++) {
                const int m = m0 + wm * 64 + i * 16 + er;
                #pragma unroll
                for (int half = 0; half < 2; half++) {
                    const float c0 = acc[i][j][half * 2 + 0] + bx;
                    const float c1 = acc[i][j][half * 2 + 1] + by;
                    __nv_bfloat16 h0, h1, l0, l1;
                    split2(c0, h0, l0); split2(c1, h1, l1);
                    __nv_bfloat162 hp(h0, h1), lp(l0, l1);
                    const size_t off = (size_t)(m + half * 8) * HIDc + n;
                    *(__nv_bfloat162*)(dh + off) = hp;
                    *(__nv_bfloat162*)(dl + off) = lp;
                }
            }
        }
    }
}

// ---------------------------------------------------------------------------
// Scores on tensor cores: s = Q.K^T (bf16x3), then e = exp(s/8 + beta*sim)
// (masked -> 0), write e to attn, per-row exp-sum atomics into g_rowsum.
// Block tile 128(q) x 128(k), K = HDc = 64 in 2 chunks of 32.
// ---------------------------------------------------------------------------
__global__ __launch_bounds__(256) void scores_mma_kernel(
    const float* __restrict__ sim, const int* __restrict__ amask,
    const float* __restrict__ beta_p, float* __restrict__ attn)
{
    const __nv_bfloat16* Qh = g_qkvh;
    const __nv_bfloat16* Ql = g_qkvl;
    const __nv_bfloat16* Kh = g_qkvh + CHUNK;
    const __nv_bfloat16* Kl = g_qkvl + CHUNK;

    constexpr int LDT = 40;
    __shared__ __nv_bfloat16 sQh[128 * LDT];
    __shared__ __nv_bfloat16 sQl[128 * LDT];
    __shared__ __nv_bfloat16 sKh[128 * LDT];
    __shared__ __nv_bfloat16 sKl[128 * LDT];

    const int tid = threadIdx.x, wid = tid >> 5, lane = tid & 31;
    const int bh = blockIdx.z, b = bh >> 4, h = bh & 15;
    const int q0 = blockIdx.y * 128, k0 = blockIdx.x * 128;
    const int wm = wid >> 2, wn = wid & 3;

    const uint32_t aQh = smem_u32(sQh), aQl = smem_u32(sQl);
    const uint32_t aKh = smem_u32(sKh), aKl = smem_u32(sKl);

    float acc[4][4][4];
    #pragma unroll
    for (int i = 0; i < 4; i++)
        #pragma unroll
        for (int j = 0; j < 4; j++)
            #pragma unroll
            for (int t = 0; t < 4; t++) acc[i][j][t] = 0.0f;

    const int r0 = tid >> 2, c0v = (tid & 3) * 8;
    const int r1 = (tid + 256) >> 2;

    const uint32_t aoff = ((lane & 15) * LDT + (lane >> 4) * 8) * 2;
    const uint32_t boff = ((lane & 7) * LDT + ((lane >> 3) & 1) * 8) * 2;

    #pragma unroll
    for (int kc = 0; kc < 2; kc++) {
        const int kb = h * HDc + kc * 32;
        {
            const size_t gQ0 = ((size_t)b * Sc + q0 + r0) * HIDc + kb + c0v;
            const size_t gQ1 = ((size_t)b * Sc + q0 + r1) * HIDc + kb + c0v;
            const size_t gK0 = ((size_t)b * Sc + k0 + r0) * HIDc + kb + c0v;
            const size_t gK1 = ((size_t)b * Sc + k0 + r1) * HIDc + kb + c0v;
            *(uint4*)&sQh[r0 * LDT + c0v] = *(const uint4*)(Qh + gQ0);
            *(uint4*)&sQh[r1 * LDT + c0v] = *(const uint4*)(Qh + gQ1);
            *(uint4*)&sQl[r0 * LDT + c0v] = *(const uint4*)(Ql + gQ0);
            *(uint4*)&sQl[r1 * LDT + c0v] = *(const uint4*)(Ql + gQ1);
            *(uint4*)&sKh[r0 * LDT + c0v] = *(const uint4*)(Kh + gK0);
            *(uint4*)&sKh[r1 * LDT + c0v] = *(const uint4*)(Kh + gK1);
            *(uint4*)&sKl[r0 * LDT + c0v] = *(const uint4*)(Kl + gK0);
            *(uint4*)&sKl[r1 * LDT + c0v] = *(const uint4*)(Kl + gK1);
        }
        __syncthreads();

        #pragma unroll
        for (int ks = 0; ks < 32; ks += 16) {
            uint32_t af[4][4], bhf[4][2], blf[4][2];
            #pragma unroll
            for (int i = 0; i < 4; i++)
                LDSM4(af[i], aQh + ((wm * 64 + i * 16) * LDT + ks) * 2 + aoff);
            #pragma unroll
            for (int j = 0; j < 4; j++)
                LDSM2(bhf[j], aKh + ((wn * 32 + j * 8) * LDT + ks) * 2 + boff);
            #pragma unroll
            for (int i = 0; i < 4; i++)
                #pragma unroll
                for (int j = 0; j < 4; j++) MMA16816(acc[i][j], af[i], bhf[j]);
            #pragma unroll
            for (int j = 0; j < 4; j++)
                LDSM2(blf[j], aKl + ((wn * 32 + j * 8) * LDT + ks) * 2 + boff);
            #pragma unroll
            for (int i = 0; i < 4; i++)
                #pragma unroll
                for (int j = 0; j < 4; j++) MMA16816(acc[i][j], af[i], blf[j]);
            #pragma unroll
            for (int i = 0; i < 4; i++)
                LDSM4(af[i], aQl + ((wm * 64 + i * 16) * LDT + ks) * 2 + aoff);
            #pragma unroll
            for (int i = 0; i < 4; i++)
                #pragma unroll
                for (int j = 0; j < 4; j++) MMA16816(acc[i][j], af[i], bhf[j]);
        }
        __syncthreads();
    }

    // Epilogue: exp((s/8) + beta*sim), mask, write, rowsum.
    const float beta = *beta_p;
    const int er = lane >> 2, ec = (lane & 3) * 2;

    int2 mk[4];
    #pragma unroll
    for (int j = 0; j < 4; j++)
        mk[j] = *(const int2*)(amask + (size_t)b * Sc + k0 + wn * 32 + j * 8 + ec);

    #pragma unroll
    for (int i = 0; i < 4; i++) {
        #pragma unroll
        for (int half = 0; half < 2; half++) {
            const int q = q0 + wm * 64 + i * 16 + half * 8 + er;
            const float* simp = sim + ((size_t)b * Sc + q) * Sc + k0 + wn * 32;
            float* ap = attn + ((size_t)bh * Sc + q) * Sc + k0 + wn * 32;
            float rs = 0.0f;
            #pragma unroll
            for (int j = 0; j < 4; j++) {
                const float2 sv = *(const float2*)(simp + j * 8 + ec);
                const float a0 = acc[i][j][half * 2 + 0];
                const float a1 = acc[i][j][half * 2 + 1];
                const float e0 = (mk[j].x == 0) ? 0.0f : __expf(fmaf(beta, sv.x, a0 * 0.125f));
                const float e1 = (mk[j].y == 0) ? 0.0f : __expf(fmaf(beta, sv.y, a1 * 0.125f));
                *(float2*)(ap + j * 8 + ec) = make_float2(e0, e1);
                rs += e0 + e1;
            }
            rs += __shfl_xor_sync(0xffffffffu, rs, 1);
            rs += __shfl_xor_sync(0xffffffffu, rs, 2);
            if ((lane & 3) == 0) atomicAdd(&g_rowsum[(size_t)bh * Sc + q], rs);
        }
    }
}

// ---------------------------------------------------------------------------
// AV on tensor cores: reads exp tile, normalizes (writes final weights back),
// splits weights to bf16 hi/lo, MMA vs split V (ldmatrix.trans from [k][d]),
// writes ctx as split bf16 for the output projection.
// Block tile 128(q) x 64(d); 8 warps 2(m) x 4(n), warp tile 64x16.
// ---------------------------------------------------------------------------
__global__ __launch_bounds__(256) void av_mma_kernel(float* __restrict__ attn)
{
    const __nv_bfloat16* Vh = g_qkvh + 2 * CHUNK;
    const __nv_bfloat16* Vl = g_qkvl + 2 * CHUNK;

    constexpr int LDA = 40, LDV = 72;
    __shared__ __nv_bfloat16 sWh[128 * LDA];
    __shared__ __nv_bfloat16 sWl[128 * LDA];
    __shared__ __nv_bfloat16 sVh[32 * LDV];
    __shared__ __nv_bfloat16 sVl[32 * LDV];
    __shared__ float inv[128];

    const int tid = threadIdx.x, wid = tid >> 5, lane = tid & 31;
    const int bh = blockIdx.z, b = bh >> 4, h = bh & 15;
    const int q0 = blockIdx.x * 128;
    const int wm = wid >> 2, wn = wid & 3;

    if (tid < 128) inv[tid] = 1.0f / g_rowsum[(size_t)bh * Sc + q0 + tid];
    __syncthreads();

    float* Abase = attn + ((size_t)bh * Sc + q0) * Sc;
    const __nv_bfloat16* Vbh = Vh + (size_t)b * Sc * HIDc + h * HDc;
    const __nv_bfloat16* Vbl = Vl + (size_t)b * Sc * HIDc + h * HDc;

    const uint32_t aWh = smem_u32(sWh), aWl = smem_u32(sWl);
    const uint32_t aVh = smem_u32(sVh), aVl = smem_u32(sVl);
    const uint32_t aoff = ((lane & 15) * LDA + (lane >> 4) * 8) * 2;

    float acc[4][2][4];
    #pragma unroll
    for (int i = 0; i < 4; i++)
        #pragma unroll
        for (int j = 0; j < 2; j++)
            #pragma unroll
            for (int t = 0; t < 4; t++) acc[i][j][t] = 0.0f;

    for (int k0c = 0; k0c < Sc; k0c += 32) {
        // Weights tile: 128 x 32 fp32 -> normalize, write back, split to smem.
        #pragma unroll
        for (int L = 0; L < 4; L++) {
            const int e = tid + L * 256;
            const int ar = e >> 3, ac = (e & 7) * 4;
            float* gp = Abase + (size_t)ar * Sc + k0c + ac;
            float4 av = *(const float4*)gp;
            const float iv = inv[ar];
            av.x *= iv; av.y *= iv; av.z *= iv; av.w *= iv;
            *(float4*)gp = av;   // final attention weights
            __nv_bfloat16 h0, h1, h2, h3, l0, l1, l2, l3;
            split2(av.x, h0, l0); split2(av.y, h1, l1);
            split2(av.z, h2, l2); split2(av.w, h3, l3);
            __nv_bfloat162 hp0(h0, h1), hp1(h2, h3), lp0(l0, l1), lp1(l2, l3);
            *(__nv_bfloat162*)&sWh[ar * LDA + ac]     = hp0;
            *(__nv_bfloat162*)&sWh[ar * LDA + ac + 2] = hp1;
            *(__nv_bfloat162*)&sWl[ar * LDA + ac]     = lp0;
            *(__nv_bfloat162*)&sWl[ar * LDA + ac + 2] = lp1;
        }
        // V tiles: 32 (k) x 64 (d) bf16 hi/lo, natural [k][d] layout.
        {
            const int vr = tid >> 3, vc = (tid & 7) * 8;
            const size_t go = (size_t)(k0c + vr) * HIDc + vc;
            *(uint4*)&sVh[vr * LDV + vc] = *(const uint4*)(Vbh + go);
            *(uint4*)&sVl[vr * LDV + vc] = *(const uint4*)(Vbl + go);
        }
        __syncthreads();

        #pragma unroll
        for (int ks = 0; ks < 32; ks += 16) {
            uint32_t ah[4][4], bhf[2][2], blf[2][2];
            #pragma unroll
            for (int i = 0; i < 4; i++)
                LDSM4(ah[i], aWh + ((wm * 64 + i * 16) * LDA + ks) * 2 + aoff);
            #pragma unroll
            for (int j = 0; j < 2; j++) {
                const uint32_t vb = ((ks + (lane & 15)) * LDV + wn * 16 + j * 8) * 2;
                LDSM2T(bhf[j], aVh + vb);
                LDSM2T(blf[j], aVl + vb);
            }
            #pragma unroll
            for (int i = 0; i < 4; i++)
                #pragma unroll
                for (int j = 0; j < 2; j++) MMA16816(acc[i][j], ah[i], bhf[j]);
            #pragma unroll
            for (int i = 0; i < 4; i++)
                #pragma unroll
                for (int j = 0; j < 2; j++) MMA16816(acc[i][j], ah[i], blf[j]);
            #pragma unroll
            for (int i = 0; i < 4; i++)
                LDSM4(ah[i], aWl + ((wm * 64 + i * 16) * LDA + ks) * 2 + aoff);
            #pragma unroll
            for (int i = 0; i < 4; i++)
                #pragma unroll
                for (int j = 0; j < 2; j++) MMA16816(acc[i][j], ah[i], bhf[j]);
        }
        __syncthreads();
    }

    // Epilogue: ctx split bf16 write. ctx[b, q, h*64 + d]
    const int er = lane >> 2, ec = (lane & 3) * 2;
    #pragma unroll
    for (int j = 0; j < 2; j++) {
        const int d = h * HDc + wn * 16 + j * 8 + ec;
        #pragma unroll
        for (int i = 0; i < 4; i++) {
            const int q = q0 + wm * 64 + i * 16 + er;
            #pragma unroll
            for (int half = 0; half < 2; half++) {
                const float c0 = acc[i][j][half * 2 + 0];
                const float c1 = acc[i][j][half * 2 + 1];
                __nv_bfloat16 h0, h1, l0, l1;
                split2(c0, h0, l0); split2(c1, h1, l1);
                __nv_bfloat162 hp(h0, h1), lp(l0, l1);
                const size_t off = ((size_t)b * Sc + q + half * 8) * HIDc + d;
                *(__nv_bfloat162*)(g_ch + off) = hp;
                *(__nv_bfloat162*)(g_cl + off) = lp;
            }
        }
    }
}

// ---------------------------------------------------------------------------
// Launcher
// ---------------------------------------------------------------------------
extern "C" void kernel_launch(void* const* d_in, const int* in_sizes, int n_in,
                              void* d_out, int out_size)
{
    const float* query = (const float*)d_in[0];
    const float* key   = (const float*)d_in[1];
    const float* value = (const float*)d_in[2];
    const int*   amask = (const int*)  d_in[3];
    const float* sim   = (const float*)d_in[4];
    const float* Wq    = (const float*)d_in[5];
    const float* bq    = (const float*)d_in[6];
    const float* Wk    = (const float*)d_in[7];
    const float* bk    = (const float*)d_in[8];
    const float* Wv    = (const float*)d_in[9];
    const float* bv    = (const float*)d_in[10];
    const float* Wo    = (const float*)d_in[11];
    const float* bo    = (const float*)d_in[12];
    const float* beta  = (const float*)d_in[13];

    float* out  = (float*)d_out;
    float* attn = out + CHUNK;   // attention_weights region [B,NH,S,S]

    zero_rowsum_kernel<<<NROWS / (256 * 4), 256>>>();

    const int cgrid = (int)(CHUNK / 1024);
    const int wgrid = (int)(WSZ / 1024);
    convert_split<<<cgrid, 256>>>(query, 0);
    convert_split<<<cgrid, 256>>>(key,   1);
    convert_split<<<cgrid, 256>>>(value, 2);
    convert_split<<<wgrid, 256>>>(Wq, 4);
    convert_split<<<wgrid, 256>>>(Wk, 5);
    convert_split<<<wgrid, 256>>>(Wv, 6);
    convert_split<<<wgrid, 256>>>(Wo, 7);

    // Projections -> split bf16 Q,K,V directly.
    dim3 gg(HIDc / 128, Mtot / 128);          // (8, 32)
    gemm_bf16x3<<<gg, 256>>>(0, 0, bq, nullptr, 0);
    gemm_bf16x3<<<gg, 256>>>(1, 1, bk, nullptr, 1);
    gemm_bf16x3<<<gg, 256>>>(2, 2, bv, nullptr, 2);

    // Scores + exp + rowsum on tensor cores.
    dim3 gs(Sc / 128, Sc / 128, Bc * NHc);    // (16, 16, 32)
    scores_mma_kernel<<<gs, 256>>>(sim, amask, beta, attn);

    // Normalize + AV on tensor cores -> ctx split bf16.
    dim3 ga(Sc / 128, 1, Bc * NHc);           // (16, 1, 32)
    av_mma_kernel<<<ga, 256>>>(attn);

    // Output projection (fp32 out).
    gemm_bf16x3<<<gg, 256>>>(3, 3, bo, out, -1);
}

// round 10
// speedup vs baseline: 1.9457x; 1.2557x over previous
#include <cuda_runtime.h>
#include <cuda_bf16.h>
#include <cstdint>

// Problem constants
constexpr int Bc   = 2;
constexpr int Sc   = 2048;
constexpr int HIDc = 1024;
constexpr int NHc  = 16;
constexpr int HDc  = 64;           // HID / NH
constexpr int Mtot = Bc * Sc;      // 4096
constexpr size_t CHUNK = (size_t)Bc * Sc * HIDc;  // 4,194,304 floats
constexpr size_t WSZ   = (size_t)HIDc * HIDc;     // 1,048,576
constexpr int NROWS = Bc * NHc * Sc;              // 65536 softmax rows

__device__ float g_rowsum[NROWS];
// bf16 split-precision scratch
__device__ __nv_bfloat16 g_inh[3 * CHUNK];   // query,key,value inputs hi
__device__ __nv_bfloat16 g_inl[3 * CHUNK];   // lo
__device__ __nv_bfloat16 g_wh[4 * WSZ];      // Wq,Wk,Wv,Wo hi
__device__ __nv_bfloat16 g_wl[4 * WSZ];      // lo
__device__ __nv_bfloat16 g_qkvh[3 * CHUNK];  // projected Q,K,V hi
__device__ __nv_bfloat16 g_qkvl[3 * CHUNK];  // lo
__device__ __nv_bfloat16 g_ch[CHUNK];        // ctx hi
__device__ __nv_bfloat16 g_cl[CHUNK];        // ctx lo

__device__ __forceinline__ uint32_t smem_u32(const void* p) {
    uint32_t a;
    asm("{ .reg .u64 t; cvta.to.shared.u64 t, %1; cvt.u32.u64 %0, t; }"
        : "=r"(a) : "l"(p));
    return a;
}

#define LDSM4(r, addr) \
    asm volatile("ldmatrix.sync.aligned.m8n8.x4.shared.b16 {%0,%1,%2,%3}, [%4];" \
        : "=r"((r)[0]), "=r"((r)[1]), "=r"((r)[2]), "=r"((r)[3]) : "r"(addr))
#define LDSM2(r, addr) \
    asm volatile("ldmatrix.sync.aligned.m8n8.x2.shared.b16 {%0,%1}, [%2];" \
        : "=r"((r)[0]), "=r"((r)[1]) : "r"(addr))
#define LDSM2T(r, addr) \
    asm volatile("ldmatrix.sync.aligned.m8n8.x2.trans.shared.b16 {%0,%1}, [%2];" \
        : "=r"((r)[0]), "=r"((r)[1]) : "r"(addr))
#define MMA16816(c, a, b) \
    asm volatile("mma.sync.aligned.m16n8k16.row.col.f32.bf16.bf16.f32 " \
        "{%0,%1,%2,%3}, {%4,%5,%6,%7}, {%8,%9}, {%0,%1,%2,%3};" \
        : "+f"((c)[0]), "+f"((c)[1]), "+f"((c)[2]), "+f"((c)[3]) \
        : "r"((a)[0]), "r"((a)[1]), "r"((a)[2]), "r"((a)[3]), \
          "r"((b)[0]), "r"((b)[1]))
#define CPA(dst, src) \
    asm volatile("cp.async.cg.shared.global [%0], [%1], 16;" :: "r"(dst), "l"(src))
#define CPC() asm volatile("cp.async.commit_group;")
#define CPW(n) asm volatile("cp.async.wait_group %0;" :: "n"(n))

__device__ __forceinline__ void split2(float x, __nv_bfloat16& h, __nv_bfloat16& l) {
    h = __float2bfloat16(x);
    l = __float2bfloat16(x - __bfloat162float(h));
}

// ---------------------------------------------------------------------------
__global__ void zero_rowsum_kernel()
{
    const int i = blockIdx.x * blockDim.x + threadIdx.x;
    ((float4*)g_rowsum)[i] = make_float4(0.f, 0.f, 0.f, 0.f);
}

// ---------------------------------------------------------------------------
// Split fp32 -> (bf16 hi, bf16 lo). dst_sel: 0..2 inputs, 4..7 weights.
// ---------------------------------------------------------------------------
__global__ __launch_bounds__(256) void convert_split(
    const float* __restrict__ src, int dst_sel)
{
    __nv_bfloat16 *h, *l;
    if (dst_sel < 3) { h = g_inh + (size_t)dst_sel * CHUNK; l = g_inl + (size_t)dst_sel * CHUNK; }
    else             { h = g_wh + (size_t)(dst_sel - 4) * WSZ; l = g_wl + (size_t)(dst_sel - 4) * WSZ; }

    const size_t i = ((size_t)blockIdx.x * 256 + threadIdx.x) * 4;
    float4 x = *(const float4*)(src + i);
    __nv_bfloat16 h0, h1, h2, h3, l0, l1, l2, l3;
    split2(x.x, h0, l0); split2(x.y, h1, l1);
    split2(x.z, h2, l2); split2(x.w, h3, l3);
    __nv_bfloat162 hp0(h0, h1), hp1(h2, h3), lp0(l0, l1), lp1(l2, l3);
    uint2 hv, lv;
    hv.x = *(uint32_t*)&hp0; hv.y = *(uint32_t*)&hp1;
    lv.x = *(uint32_t*)&lp0; lv.y = *(uint32_t*)&lp1;
    *(uint2*)(h + i) = hv;
    *(uint2*)(l + i) = lv;
}

// ---------------------------------------------------------------------------
// mma.sync bf16x3 GEMM with cp.async double buffering.
// Block tile 128x128, BK=32, 8 warps 2(m) x 4(n).
// Dynamic smem: 2 buffers x 4 tiles x (128 x 40 halves) = 81920 B.
// ---------------------------------------------------------------------------
constexpr int GEMM_SMEM = 2 * 4 * 128 * 40 * 2;   // 81920

__global__ __launch_bounds__(256) void gemm_bf16x3(
    int a_sel, int w_sel, const float* __restrict__ bias,
    float* __restrict__ Cext, int osel)
{
    const __nv_bfloat16* Ah = (a_sel < 3) ? g_inh + (size_t)a_sel * CHUNK : g_ch;
    const __nv_bfloat16* Al = (a_sel < 3) ? g_inl + (size_t)a_sel * CHUNK : g_cl;
    const __nv_bfloat16* Wh = g_wh + (size_t)w_sel * WSZ;
    const __nv_bfloat16* Wl = g_wl + (size_t)w_sel * WSZ;

    extern __shared__ __align__(128) char dsm[];
    constexpr int LDT = 40;                  // halves; 80 B row stride
    constexpr int TILE = 128 * LDT * 2;      // 10240 B
    constexpr int BUF  = 4 * TILE;           // 40960 B
    const uint32_t sb = smem_u32(dsm);

    const int tid = threadIdx.x, wid = tid >> 5, lane = tid & 31;
    const int m0 = blockIdx.y * 128, n0 = blockIdx.x * 128;
    const int wm = wid >> 2, wn = wid & 3;

    float acc[4][4][4];
    #pragma unroll
    for (int i = 0; i < 4; i++)
        #pragma unroll
        for (int j = 0; j < 4; j++)
            #pragma unroll
            for (int t = 0; t < 4; t++) acc[i][j][t] = 0.0f;

    const int r0 = tid >> 2, c0v = (tid & 3) * 8;   // halves
    const int r1 = r0 + 64;
    const uint32_t sOff0 = r0 * (LDT * 2) + c0v * 2;
    const uint32_t sOff1 = r1 * (LDT * 2) + c0v * 2;

    const uint32_t aoff = ((lane & 15) * LDT + (lane >> 4) * 8) * 2;
    const uint32_t boff = ((lane & 7) * LDT + ((lane >> 3) & 1) * 8) * 2;

    auto issue = [&](int kc, int buf) {
        const int kb = kc * 32;
        const uint32_t base = sb + buf * BUF;
        const size_t gA0 = (size_t)(m0 + r0) * HIDc + kb + c0v;
        const size_t gA1 = (size_t)(m0 + r1) * HIDc + kb + c0v;
        const size_t gB0 = (size_t)(n0 + r0) * HIDc + kb + c0v;
        const size_t gB1 = (size_t)(n0 + r1) * HIDc + kb + c0v;
        CPA(base + 0 * TILE + sOff0, Ah + gA0);
        CPA(base + 0 * TILE + sOff1, Ah + gA1);
        CPA(base + 1 * TILE + sOff0, Al + gA0);
        CPA(base + 1 * TILE + sOff1, Al + gA1);
        CPA(base + 2 * TILE + sOff0, Wh + gB0);
        CPA(base + 2 * TILE + sOff1, Wh + gB1);
        CPA(base + 3 * TILE + sOff0, Wl + gB0);
        CPA(base + 3 * TILE + sOff1, Wl + gB1);
    };

    issue(0, 0); CPC();

    for (int kc = 0; kc < 32; kc++) {
        const int cur = kc & 1;
        if (kc < 31) { issue(kc + 1, cur ^ 1); CPC(); CPW(1); }
        else         { CPW(0); }
        __syncthreads();

        const uint32_t bA = sb + cur * BUF;
        #pragma unroll
        for (int ks = 0; ks < 32; ks += 16) {
            uint32_t af[4][4], bh[4][2], bl[4][2];
            #pragma unroll
            for (int i = 0; i < 4; i++)
                LDSM4(af[i], bA + 0 * TILE + ((wm * 64 + i * 16) * LDT + ks) * 2 + aoff);
            #pragma unroll
            for (int j = 0; j < 4; j++)
                LDSM2(bh[j], bA + 2 * TILE + ((wn * 32 + j * 8) * LDT + ks) * 2 + boff);
            #pragma unroll
            for (int i = 0; i < 4; i++)
                #pragma unroll
                for (int j = 0; j < 4; j++) MMA16816(acc[i][j], af[i], bh[j]);
            #pragma unroll
            for (int j = 0; j < 4; j++)
                LDSM2(bl[j], bA + 3 * TILE + ((wn * 32 + j * 8) * LDT + ks) * 2 + boff);
            #pragma unroll
            for (int i = 0; i < 4; i++)
                #pragma unroll
                for (int j = 0; j < 4; j++) MMA16816(acc[i][j], af[i], bl[j]);
            #pragma unroll
            for (int i = 0; i < 4; i++)
                LDSM4(af[i], bA + 1 * TILE + ((wm * 64 + i * 16) * LDT + ks) * 2 + aoff);
            #pragma unroll
            for (int i = 0; i < 4; i++)
                #pragma unroll
                for (int j = 0; j < 4; j++) MMA16816(acc[i][j], af[i], bh[j]);
        }
        __syncthreads();
    }

    const int er = lane >> 2, ec = (lane & 3) * 2;
    if (osel < 0) {
        #pragma unroll
        for (int j = 0; j < 4; j++) {
            const int n = n0 + wn * 32 + j * 8 + ec;
            const float bx = bias[n], by = bias[n + 1];
            #pragma unroll
            for (int i = 0; i < 4; i++) {
                const int m = m0 + wm * 64 + i * 16 + er;
                *(float2*)(Cext + (size_t)m * HIDc + n) =
                    make_float2(acc[i][j][0] + bx, acc[i][j][1] + by);
                *(float2*)(Cext + (size_t)(m + 8) * HIDc + n) =
                    make_float2(acc[i][j][2] + bx, acc[i][j][3] + by);
            }
        }
    } else {
        __nv_bfloat16* dh = g_qkvh + (size_t)osel * CHUNK;
        __nv_bfloat16* dl = g_qkvl + (size_t)osel * CHUNK;
        #pragma unroll
        for (int j = 0; j < 4; j++) {
            const int n = n0 + wn * 32 + j * 8 + ec;
            const float bx = bias[n], by = bias[n + 1];
            #pragma unroll
            for (int i = 0; i < 4; i++) {
                const int m = m0 + wm * 64 + i * 16 + er;
                #pragma unroll
                for (int half = 0; half < 2; half++) {
                    const float c0 = acc[i][j][half * 2 + 0] + bx;
                    const float c1 = acc[i][j][half * 2 + 1] + by;
                    __nv_bfloat16 h0, h1, l0, l1;
                    split2(c0, h0, l0); split2(c1, h1, l1);
                    __nv_bfloat162 hp(h0, h1), lp(l0, l1);
                    const size_t off = (size_t)(m + half * 8) * HIDc + n;
                    *(__nv_bfloat162*)(dh + off) = hp;
                    *(__nv_bfloat162*)(dl + off) = lp;
                }
            }
        }
    }
}

// ---------------------------------------------------------------------------
// Scores on tensor cores, one-shot K: full HD=64 in smem (one cp.async phase),
// then 4 uninterrupted MMA steps. Epilogue: exp(s/8 + beta*sim), mask, rowsum.
// Dynamic smem: 4 tiles x (128 x 72 halves) = 73728 B.
// ---------------------------------------------------------------------------
constexpr int SC_SMEM = 4 * 128 * 72 * 2;   // 73728

__global__ __launch_bounds__(256) void scores_mma_kernel(
    const float* __restrict__ sim, const int* __restrict__ amask,
    const float* __restrict__ beta_p, float* __restrict__ attn)
{
    extern __shared__ __align__(128) char dsm[];
    constexpr int LDT = 72;                 // halves; 144 B row stride
    constexpr int TILE = 128 * LDT * 2;     // 18432 B
    const uint32_t sb = smem_u32(dsm);

    const int tid = threadIdx.x, wid = tid >> 5, lane = tid & 31;
    const int bh = blockIdx.z, b = bh >> 4, h = bh & 15;
    const int q0 = blockIdx.y * 128, k0 = blockIdx.x * 128;
    const int wm = wid >> 2, wn = wid & 3;

    // One cp.async phase: 4 tiles (Qh, Ql, Kh, Kl), 16 x 16B per thread.
    {
        const __nv_bfloat16* srcs[4] = {g_qkvh, g_qkvl, g_qkvh + CHUNK, g_qkvl + CHUNK};
        const int rb[4] = {q0, q0, k0, k0};
        #pragma unroll
        for (int L = 0; L < 16; L++) {
            const int e = tid + L * 256;
            const int t = e >> 10, r = (e >> 3) & 127, c = e & 7;
            const size_t g = ((size_t)b * Sc + rb[t] + r) * HIDc + h * HDc + c * 8;
            CPA(sb + t * TILE + r * (LDT * 2) + c * 16, srcs[t] + g);
        }
        CPC(); CPW(0);
    }
    __syncthreads();

    float acc[4][4][4];
    #pragma unroll
    for (int i = 0; i < 4; i++)
        #pragma unroll
        for (int j = 0; j < 4; j++)
            #pragma unroll
            for (int t = 0; t < 4; t++) acc[i][j][t] = 0.0f;

    const uint32_t aoff = ((lane & 15) * LDT + (lane >> 4) * 8) * 2;
    const uint32_t boff = ((lane & 7) * LDT + ((lane >> 3) & 1) * 8) * 2;
    const uint32_t aQh = sb, aQl = sb + TILE, aKh = sb + 2 * TILE, aKl = sb + 3 * TILE;

    #pragma unroll
    for (int ks = 0; ks < 64; ks += 16) {
        uint32_t af[4][4], bhf[4][2], blf[4][2];
        #pragma unroll
        for (int i = 0; i < 4; i++)
            LDSM4(af[i], aQh + ((wm * 64 + i * 16) * LDT + ks) * 2 + aoff);
        #pragma unroll
        for (int j = 0; j < 4; j++)
            LDSM2(bhf[j], aKh + ((wn * 32 + j * 8) * LDT + ks) * 2 + boff);
        #pragma unroll
        for (int i = 0; i < 4; i++)
            #pragma unroll
            for (int j = 0; j < 4; j++) MMA16816(acc[i][j], af[i], bhf[j]);
        #pragma unroll
        for (int j = 0; j < 4; j++)
            LDSM2(blf[j], aKl + ((wn * 32 + j * 8) * LDT + ks) * 2 + boff);
        #pragma unroll
        for (int i = 0; i < 4; i++)
            #pragma unroll
            for (int j = 0; j < 4; j++) MMA16816(acc[i][j], af[i], blf[j]);
        #pragma unroll
        for (int i = 0; i < 4; i++)
            LDSM4(af[i], aQl + ((wm * 64 + i * 16) * LDT + ks) * 2 + aoff);
        #pragma unroll
        for (int i = 0; i < 4; i++)
            #pragma unroll
            for (int j = 0; j < 4; j++) MMA16816(acc[i][j], af[i], bhf[j]);
    }

    // Epilogue: exp((s/8) + beta*sim), mask, write, rowsum.
    const float beta = *beta_p;
    const int er = lane >> 2, ec = (lane & 3) * 2;

    int2 mk[4];
    #pragma unroll
    for (int j = 0; j < 4; j++)
        mk[j] = *(const int2*)(amask + (size_t)b * Sc + k0 + wn * 32 + j * 8 + ec);

    #pragma unroll
    for (int i = 0; i < 4; i++) {
        #pragma unroll
        for (int half = 0; half < 2; half++) {
            const int q = q0 + wm * 64 + i * 16 + half * 8 + er;
            const float* simp = sim + ((size_t)b * Sc + q) * Sc + k0 + wn * 32;
            float* ap = attn + ((size_t)bh * Sc + q) * Sc + k0 + wn * 32;
            float rs = 0.0f;
            #pragma unroll
            for (int j = 0; j < 4; j++) {
                const float2 sv = *(const float2*)(simp + j * 8 + ec);
                const float a0 = acc[i][j][half * 2 + 0];
                const float a1 = acc[i][j][half * 2 + 1];
                const float e0 = (mk[j].x == 0) ? 0.0f : __expf(fmaf(beta, sv.x, a0 * 0.125f));
                const float e1 = (mk[j].y == 0) ? 0.0f : __expf(fmaf(beta, sv.y, a1 * 0.125f));
                *(float2*)(ap + j * 8 + ec) = make_float2(e0, e1);
                rs += e0 + e1;
            }
            rs += __shfl_xor_sync(0xffffffffu, rs, 1);
            rs += __shfl_xor_sync(0xffffffffu, rs, 2);
            if ((lane & 3) == 0) atomicAdd(&g_rowsum[(size_t)bh * Sc + q], rs);
        }
    }
}

// ---------------------------------------------------------------------------
// AV on tensor cores with cp.async staging:
// exp tile staged to smem (cp.async), normalized (final weights STG'd),
// split to bf16 smem; V double-buffered via cp.async; MMA bf16x3.
// Dynamic smem layout (57856 B):
//   [0)       stag   : 128 x 36 fp32     (18432)
//   [18432)   sWh    : 128 x 40 halves   (10240)
//   [28672)   sWl    : 128 x 40 halves   (10240)
//   [38912)   V bufs : 2 x (Vh 4608 + Vl 4608)  (18432)
//   [57344)   inv    : 128 fp32          (512)
// ---------------------------------------------------------------------------
constexpr int AV_SMEM = 57856;

__global__ __launch_bounds__(256) void av_mma_kernel(float* __restrict__ attn)
{
    extern __shared__ __align__(128) char dsm[];
    constexpr int LDA = 40;   // halves (80 B)
    constexpr int LDV = 72;   // halves (144 B)
    constexpr uint32_t OF_WH = 18432, OF_WL = 28672, OF_V = 38912, OF_INV = 57344;
    constexpr uint32_t VBUF = 9216, OF_VL = 4608;
    const uint32_t sb = smem_u32(dsm);
    float* s_inv = (float*)(dsm + OF_INV);

    const int tid = threadIdx.x, wid = tid >> 5, lane = tid & 31;
    const int bh = blockIdx.z, b = bh >> 4, h = bh & 15;
    const int q0 = blockIdx.x * 128;
    const int wm = wid >> 2, wn = wid & 3;

    if (tid < 128) s_inv[tid] = 1.0f / g_rowsum[(size_t)bh * Sc + q0 + tid];

    float* Abase = attn + ((size_t)bh * Sc + q0) * Sc;
    const __nv_bfloat16* Vbh = g_qkvh + 2 * CHUNK + (size_t)b * Sc * HIDc + h * HDc;
    const __nv_bfloat16* Vbl = g_qkvl + 2 * CHUNK + (size_t)b * Sc * HIDc + h * HDc;

    // Per-thread load coords.
    const int sr = tid >> 3, sc = tid & 7;          // staging: rows x 8 col-quads
    const int vr = tid >> 3, vc = tid & 7;          // V: 32 rows x 8 col-quads

    auto issue = [&](int kc, int vbuf) {
        const int kb = kc * 32;
        #pragma unroll
        for (int L = 0; L < 4; L++) {
            const int r = sr + L * 32;
            CPA(sb + r * 144 + sc * 16, Abase + (size_t)r * Sc + kb + sc * 4);
        }
        const size_t gv = (size_t)(kb + vr) * HIDc + vc * 8;
        CPA(sb + OF_V + vbuf * VBUF + vr * 144 + vc * 16, Vbh + gv);
        CPA(sb + OF_V + vbuf * VBUF + OF_VL + vr * 144 + vc * 16, Vbl + gv);
    };

    issue(0, 0); CPC();

    const uint32_t aoff = ((lane & 15) * LDA + (lane >> 4) * 8) * 2;

    float acc[4][2][4];
    #pragma unroll
    for (int i = 0; i < 4; i++)
        #pragma unroll
        for (int j = 0; j < 2; j++)
            #pragma unroll
            for (int t = 0; t < 4; t++) acc[i][j][t] = 0.0f;

    for (int kc = 0; kc < 64; kc++) {
        CPW(0);
        __syncthreads();

        // Process staging: normalize, STG final weights, split into sWh/sWl.
        #pragma unroll
        for (int L = 0; L < 4; L++) {
            const int e = tid + L * 256;
            const int ar = e >> 3, ac = (e & 7) * 4;
            float4 av = *(const float4*)(dsm + ar * 144 + ac * 4);
            const float iv = s_inv[ar];
            av.x *= iv; av.y *= iv; av.z *= iv; av.w *= iv;
            *(float4*)(Abase + (size_t)ar * Sc + kc * 32 + ac) = av;
            __nv_bfloat16 h0, h1, h2, h3, l0, l1, l2, l3;
            split2(av.x, h0, l0); split2(av.y, h1, l1);
            split2(av.z, h2, l2); split2(av.w, h3, l3);
            __nv_bfloat162 hp0(h0, h1), hp1(h2, h3), lp0(l0, l1), lp1(l2, l3);
            *(__nv_bfloat162*)(dsm + OF_WH + (ar * LDA + ac) * 2)     = hp0;
            *(__nv_bfloat162*)(dsm + OF_WH + (ar * LDA + ac + 2) * 2) = hp1;
            *(__nv_bfloat162*)(dsm + OF_WL + (ar * LDA + ac) * 2)     = lp0;
            *(__nv_bfloat162*)(dsm + OF_WL + (ar * LDA + ac + 2) * 2) = lp1;
        }
        __syncthreads();

        if (kc < 63) { issue(kc + 1, (kc + 1) & 1); CPC(); }

        const uint32_t vb0 = sb + OF_V + (kc & 1) * VBUF;
        #pragma unroll
        for (int ks = 0; ks < 32; ks += 16) {
            uint32_t ah[4][4], bhf[2][2], blf[2][2];
            #pragma unroll
            for (int i = 0; i < 4; i++)
                LDSM4(ah[i], sb + OF_WH + ((wm * 64 + i * 16) * LDA + ks) * 2 + aoff);
            #pragma unroll
            for (int j = 0; j < 2; j++) {
                const uint32_t vbo = ((ks + (lane & 15)) * LDV + wn * 16 + j * 8) * 2;
                LDSM2T(bhf[j], vb0 + vbo);
                LDSM2T(blf[j], vb0 + OF_VL + vbo);
            }
            #pragma unroll
            for (int i = 0; i < 4; i++)
                #pragma unroll
                for (int j = 0; j < 2; j++) MMA16816(acc[i][j], ah[i], bhf[j]);
            #pragma unroll
            for (int i = 0; i < 4; i++)
                #pragma unroll
                for (int j = 0; j < 2; j++) MMA16816(acc[i][j], ah[i], blf[j]);
            #pragma unroll
            for (int i = 0; i < 4; i++)
                LDSM4(ah[i], sb + OF_WL + ((wm * 64 + i * 16) * LDA + ks) * 2 + aoff);
            #pragma unroll
            for (int i = 0; i < 4; i++)
                #pragma unroll
                for (int j = 0; j < 2; j++) MMA16816(acc[i][j], ah[i], bhf[j]);
        }
        __syncthreads();
    }

    // Epilogue: ctx split bf16 write. ctx[b, q, h*64 + d]
    const int er = lane >> 2, ec = (lane & 3) * 2;
    #pragma unroll
    for (int j = 0; j < 2; j++) {
        const int d = h * HDc + wn * 16 + j * 8 + ec;
        #pragma unroll
        for (int i = 0; i < 4; i++) {
            const int q = q0 + wm * 64 + i * 16 + er;
            #pragma unroll
            for (int half = 0; half < 2; half++) {
                const float c0 = acc[i][j][half * 2 + 0];
                const float c1 = acc[i][j][half * 2 + 1];
                __nv_bfloat16 h0, h1, l0, l1;
                split2(c0, h0, l0); split2(c1, h1, l1);
                __nv_bfloat162 hp(h0, h1), lp(l0, l1);
                const size_t off = ((size_t)b * Sc + q + half * 8) * HIDc + d;
                *(__nv_bfloat162*)(g_ch + off) = hp;
                *(__nv_bfloat162*)(g_cl + off) = lp;
            }
        }
    }
}

// ---------------------------------------------------------------------------
// Launcher
// ---------------------------------------------------------------------------
extern "C" void kernel_launch(void* const* d_in, const int* in_sizes, int n_in,
                              void* d_out, int out_size)
{
    const float* query = (const float*)d_in[0];
    const float* key   = (const float*)d_in[1];
    const float* value = (const float*)d_in[2];
    const int*   amask = (const int*)  d_in[3];
    const float* sim   = (const float*)d_in[4];
    const float* Wq    = (const float*)d_in[5];
    const float* bq    = (const float*)d_in[6];
    const float* Wk    = (const float*)d_in[7];
    const float* bk    = (const float*)d_in[8];
    const float* Wv    = (const float*)d_in[9];
    const float* bv    = (const float*)d_in[10];
    const float* Wo    = (const float*)d_in[11];
    const float* bo    = (const float*)d_in[12];
    const float* beta  = (const float*)d_in[13];

    float* out  = (float*)d_out;
    float* attn = out + CHUNK;   // attention_weights region [B,NH,S,S]

    cudaFuncSetAttribute(gemm_bf16x3,
                         cudaFuncAttributeMaxDynamicSharedMemorySize, GEMM_SMEM);
    cudaFuncSetAttribute(scores_mma_kernel,
                         cudaFuncAttributeMaxDynamicSharedMemorySize, SC_SMEM);
    cudaFuncSetAttribute(av_mma_kernel,
                         cudaFuncAttributeMaxDynamicSharedMemorySize, AV_SMEM);

    zero_rowsum_kernel<<<NROWS / (256 * 4), 256>>>();

    const int cgrid = (int)(CHUNK / 1024);
    const int wgrid = (int)(WSZ / 1024);
    convert_split<<<cgrid, 256>>>(query, 0);
    convert_split<<<cgrid, 256>>>(key,   1);
    convert_split<<<cgrid, 256>>>(value, 2);
    convert_split<<<wgrid, 256>>>(Wq, 4);
    convert_split<<<wgrid, 256>>>(Wk, 5);
    convert_split<<<wgrid, 256>>>(Wv, 6);
    convert_split<<<wgrid, 256>>>(Wo, 7);

    // Projections -> split bf16 Q,K,V directly.
    dim3 gg(HIDc / 128, Mtot / 128);          // (8, 32)
    gemm_bf16x3<<<gg, 256, GEMM_SMEM>>>(0, 0, bq, nullptr, 0);
    gemm_bf16x3<<<gg, 256, GEMM_SMEM>>>(1, 1, bk, nullptr, 1);
    gemm_bf16x3<<<gg, 256, GEMM_SMEM>>>(2, 2, bv, nullptr, 2);

    // Scores + exp + rowsum on tensor cores.
    dim3 gs(Sc / 128, Sc / 128, Bc * NHc);    // (16, 16, 32)
    scores_mma_kernel<<<gs, 256, SC_SMEM>>>(sim, amask, beta, attn);

    // Normalize + AV on tensor cores -> ctx split bf16.
    dim3 ga(Sc / 128, 1, Bc * NHc);           // (16, 1, 32)
    av_mma_kernel<<<ga, 256, AV_SMEM>>>(attn);

    // Output projection (fp32 out).
    gemm_bf16x3<<<gg, 256, GEMM_SMEM>>>(3, 3, bo, out, -1);
}

// round 11
// speedup vs baseline: 1.9852x; 1.0203x over previous
#include <cuda_runtime.h>
#include <cuda_bf16.h>
#include <cstdint>

// Problem constants
constexpr int Bc   = 2;
constexpr int Sc   = 2048;
constexpr int HIDc = 1024;
constexpr int NHc  = 16;
constexpr int HDc  = 64;           // HID / NH
constexpr int Mtot = Bc * Sc;      // 4096
constexpr size_t CHUNK = (size_t)Bc * Sc * HIDc;  // 4,194,304 floats
constexpr size_t WSZ   = (size_t)HIDc * HIDc;     // 1,048,576
constexpr int NROWS = Bc * NHc * Sc;              // 65536 softmax rows

__device__ float g_rowsum[NROWS];
// bf16 split-precision scratch
__device__ __nv_bfloat16 g_inh[3 * CHUNK];   // query,key,value inputs hi
__device__ __nv_bfloat16 g_inl[3 * CHUNK];   // lo
__device__ __nv_bfloat16 g_wh[4 * WSZ];      // Wq,Wk,Wv,Wo hi
__device__ __nv_bfloat16 g_wl[4 * WSZ];      // lo
__device__ __nv_bfloat16 g_qkvh[3 * CHUNK];  // projected Q,K,V hi
__device__ __nv_bfloat16 g_qkvl[3 * CHUNK];  // lo
__device__ __nv_bfloat16 g_ch[CHUNK];        // ctx hi
__device__ __nv_bfloat16 g_cl[CHUNK];        // ctx lo

__device__ __forceinline__ uint32_t smem_u32(const void* p) {
    uint32_t a;
    asm("{ .reg .u64 t; cvta.to.shared.u64 t, %1; cvt.u32.u64 %0, t; }"
        : "=r"(a) : "l"(p));
    return a;
}

#define LDSM4(r, addr) \
    asm volatile("ldmatrix.sync.aligned.m8n8.x4.shared.b16 {%0,%1,%2,%3}, [%4];" \
        : "=r"((r)[0]), "=r"((r)[1]), "=r"((r)[2]), "=r"((r)[3]) : "r"(addr))
#define LDSM2(r, addr) \
    asm volatile("ldmatrix.sync.aligned.m8n8.x2.shared.b16 {%0,%1}, [%2];" \
        : "=r"((r)[0]), "=r"((r)[1]) : "r"(addr))
#define LDSM2T(r, addr) \
    asm volatile("ldmatrix.sync.aligned.m8n8.x2.trans.shared.b16 {%0,%1}, [%2];" \
        : "=r"((r)[0]), "=r"((r)[1]) : "r"(addr))
#define MMA16816(c, a, b) \
    asm volatile("mma.sync.aligned.m16n8k16.row.col.f32.bf16.bf16.f32 " \
        "{%0,%1,%2,%3}, {%4,%5,%6,%7}, {%8,%9}, {%0,%1,%2,%3};" \
        : "+f"((c)[0]), "+f"((c)[1]), "+f"((c)[2]), "+f"((c)[3]) \
        : "r"((a)[0]), "r"((a)[1]), "r"((a)[2]), "r"((a)[3]), \
          "r"((b)[0]), "r"((b)[1]))
#define CPA(dst, src) \
    asm volatile("cp.async.cg.shared.global [%0], [%1], 16;" :: "r"(dst), "l"(src))
#define CPC() asm volatile("cp.async.commit_group;")
#define CPW(n) asm volatile("cp.async.wait_group %0;" :: "n"(n))

__device__ __forceinline__ void split2(float x, __nv_bfloat16& h, __nv_bfloat16& l) {
    h = __float2bfloat16(x);
    l = __float2bfloat16(x - __bfloat162float(h));
}

// ---------------------------------------------------------------------------
// Single merged conversion kernel: splits the 3 inputs and 4 weights into
// bf16 hi/lo, and zeroes g_rowsum. Flattened element index decides region.
// grid = (3*CHUNK + 4*WSZ) / 1024 blocks of 256 (4 floats/thread).
// ---------------------------------------------------------------------------
constexpr int CVT_BLOCKS = (int)((3 * CHUNK + 4 * WSZ) / 1024);

__global__ __launch_bounds__(256) void convert_all(
    const float* __restrict__ q, const float* __restrict__ k,
    const float* __restrict__ v, const float* __restrict__ wq,
    const float* __restrict__ wk, const float* __restrict__ wv,
    const float* __restrict__ wo)
{
    const size_t gid = (size_t)blockIdx.x * 256 + threadIdx.x;
    if (gid < NROWS / 4)
        ((float4*)g_rowsum)[gid] = make_float4(0.f, 0.f, 0.f, 0.f);

    const size_t i = gid * 4;
    const float* src;
    __nv_bfloat16 *h, *l;
    size_t off;
    if (i < 3 * CHUNK) {
        const int s = (int)(i / CHUNK);
        off = i - (size_t)s * CHUNK;
        src = (s == 0) ? q : (s == 1) ? k : v;
        h = g_inh + (size_t)s * CHUNK; l = g_inl + (size_t)s * CHUNK;
    } else {
        const size_t i2 = i - 3 * CHUNK;
        const int s = (int)(i2 / WSZ);
        off = i2 - (size_t)s * WSZ;
        src = (s == 0) ? wq : (s == 1) ? wk : (s == 2) ? wv : wo;
        h = g_wh + (size_t)s * WSZ; l = g_wl + (size_t)s * WSZ;
    }

    float4 x = *(const float4*)(src + off);
    __nv_bfloat16 h0, h1, h2, h3, l0, l1, l2, l3;
    split2(x.x, h0, l0); split2(x.y, h1, l1);
    split2(x.z, h2, l2); split2(x.w, h3, l3);
    __nv_bfloat162 hp0(h0, h1), hp1(h2, h3), lp0(l0, l1), lp1(l2, l3);
    uint2 hv, lv;
    hv.x = *(uint32_t*)&hp0; hv.y = *(uint32_t*)&hp1;
    lv.x = *(uint32_t*)&lp0; lv.y = *(uint32_t*)&lp1;
    *(uint2*)(h + off) = hv;
    *(uint2*)(l + off) = lv;
}

// ---------------------------------------------------------------------------
// mma.sync bf16x3 GEMM with cp.async double buffering.
// Block tile 128x128, BK=32, 8 warps 2(m) x 4(n).
// qkv_mode != 0: grid.z in {0,1,2} picks (input, weight, bias, split output).
// qkv_mode == 0: ctx @ Wo -> fp32 Cext + bias b0.
// Dynamic smem: 2 buffers x 4 tiles x (128 x 40 halves) = 81920 B.
// ---------------------------------------------------------------------------
constexpr int GEMM_SMEM = 2 * 4 * 128 * 40 * 2;   // 81920

__global__ __launch_bounds__(256) void gemm_bf16x3(
    const float* __restrict__ b0, const float* __restrict__ b1,
    const float* __restrict__ b2, float* __restrict__ Cext, int qkv_mode)
{
    int a_sel, w_sel, osel;
    const float* bias;
    if (qkv_mode) {
        a_sel = w_sel = osel = blockIdx.z;
        bias = (blockIdx.z == 0) ? b0 : (blockIdx.z == 1) ? b1 : b2;
    } else {
        a_sel = 3; w_sel = 3; osel = -1; bias = b0;
    }
    const __nv_bfloat16* Ah = (a_sel < 3) ? g_inh + (size_t)a_sel * CHUNK : g_ch;
    const __nv_bfloat16* Al = (a_sel < 3) ? g_inl + (size_t)a_sel * CHUNK : g_cl;
    const __nv_bfloat16* Wh = g_wh + (size_t)w_sel * WSZ;
    const __nv_bfloat16* Wl = g_wl + (size_t)w_sel * WSZ;

    extern __shared__ __align__(128) char dsm[];
    constexpr int LDT = 40;                  // halves; 80 B row stride
    constexpr int TILE = 128 * LDT * 2;      // 10240 B
    constexpr int BUF  = 4 * TILE;           // 40960 B
    const uint32_t sb = smem_u32(dsm);

    const int tid = threadIdx.x, wid = tid >> 5, lane = tid & 31;
    const int m0 = blockIdx.y * 128, n0 = blockIdx.x * 128;
    const int wm = wid >> 2, wn = wid & 3;

    float acc[4][4][4];
    #pragma unroll
    for (int i = 0; i < 4; i++)
        #pragma unroll
        for (int j = 0; j < 4; j++)
            #pragma unroll
            for (int t = 0; t < 4; t++) acc[i][j][t] = 0.0f;

    const int r0 = tid >> 2, c0v = (tid & 3) * 8;   // halves
    const int r1 = r0 + 64;
    const uint32_t sOff0 = r0 * (LDT * 2) + c0v * 2;
    const uint32_t sOff1 = r1 * (LDT * 2) + c0v * 2;

    const uint32_t aoff = ((lane & 15) * LDT + (lane >> 4) * 8) * 2;
    const uint32_t boff = ((lane & 7) * LDT + ((lane >> 3) & 1) * 8) * 2;

    auto issue = [&](int kc, int buf) {
        const int kb = kc * 32;
        const uint32_t base = sb + buf * BUF;
        const size_t gA0 = (size_t)(m0 + r0) * HIDc + kb + c0v;
        const size_t gA1 = (size_t)(m0 + r1) * HIDc + kb + c0v;
        const size_t gB0 = (size_t)(n0 + r0) * HIDc + kb + c0v;
        const size_t gB1 = (size_t)(n0 + r1) * HIDc + kb + c0v;
        CPA(base + 0 * TILE + sOff0, Ah + gA0);
        CPA(base + 0 * TILE + sOff1, Ah + gA1);
        CPA(base + 1 * TILE + sOff0, Al + gA0);
        CPA(base + 1 * TILE + sOff1, Al + gA1);
        CPA(base + 2 * TILE + sOff0, Wh + gB0);
        CPA(base + 2 * TILE + sOff1, Wh + gB1);
        CPA(base + 3 * TILE + sOff0, Wl + gB0);
        CPA(base + 3 * TILE + sOff1, Wl + gB1);
    };

    issue(0, 0); CPC();

    for (int kc = 0; kc < 32; kc++) {
        const int cur = kc & 1;
        if (kc < 31) { issue(kc + 1, cur ^ 1); CPC(); CPW(1); }
        else         { CPW(0); }
        __syncthreads();

        const uint32_t bA = sb + cur * BUF;
        #pragma unroll
        for (int ks = 0; ks < 32; ks += 16) {
            uint32_t af[4][4], bh[4][2], bl[4][2];
            #pragma unroll
            for (int i = 0; i < 4; i++)
                LDSM4(af[i], bA + 0 * TILE + ((wm * 64 + i * 16) * LDT + ks) * 2 + aoff);
            #pragma unroll
            for (int j = 0; j < 4; j++)
                LDSM2(bh[j], bA + 2 * TILE + ((wn * 32 + j * 8) * LDT + ks) * 2 + boff);
            #pragma unroll
            for (int i = 0; i < 4; i++)
                #pragma unroll
                for (int j = 0; j < 4; j++) MMA16816(acc[i][j], af[i], bh[j]);
            #pragma unroll
            for (int j = 0; j < 4; j++)
                LDSM2(bl[j], bA + 3 * TILE + ((wn * 32 + j * 8) * LDT + ks) * 2 + boff);
            #pragma unroll
            for (int i = 0; i < 4; i++)
                #pragma unroll
                for (int j = 0; j < 4; j++) MMA16816(acc[i][j], af[i], bl[j]);
            #pragma unroll
            for (int i = 0; i < 4; i++)
                LDSM4(af[i], bA + 1 * TILE + ((wm * 64 + i * 16) * LDT + ks) * 2 + aoff);
            #pragma unroll
            for (int i = 0; i < 4; i++)
                #pragma unroll
                for (int j = 0; j < 4; j++) MMA16816(acc[i][j], af[i], bh[j]);
        }
        __syncthreads();
    }

    const int er = lane >> 2, ec = (lane & 3) * 2;
    if (osel < 0) {
        #pragma unroll
        for (int j = 0; j < 4; j++) {
            const int n = n0 + wn * 32 + j * 8 + ec;
            const float bx = bias[n], by = bias[n + 1];
            #pragma unroll
            for (int i = 0; i < 4; i++) {
                const int m = m0 + wm * 64 + i * 16 + er;
                *(float2*)(Cext + (size_t)m * HIDc + n) =
                    make_float2(acc[i][j][0] + bx, acc[i][j][1] + by);
                *(float2*)(Cext + (size_t)(m + 8) * HIDc + n) =
                    make_float2(acc[i][j][2] + bx, acc[i][j][3] + by);
            }
        }
    } else {
        __nv_bfloat16* dh = g_qkvh + (size_t)osel * CHUNK;
        __nv_bfloat16* dl = g_qkvl + (size_t)osel * CHUNK;
        #pragma unroll
        for (int j = 0; j < 4; j++) {
            const int n = n0 + wn * 32 + j * 8 + ec;
            const float bx = bias[n], by = bias[n + 1];
            #pragma unroll
            for (int i = 0; i < 4; i++) {
                const int m = m0 + wm * 64 + i * 16 + er;
                #pragma unroll
                for (int half = 0; half < 2; half++) {
                    const float c0 = acc[i][j][half * 2 + 0] + bx;
                    const float c1 = acc[i][j][half * 2 + 1] + by;
                    __nv_bfloat16 h0, h1, l0, l1;
                    split2(c0, h0, l0); split2(c1, h1, l1);
                    __nv_bfloat162 hp(h0, h1), lp(l0, l1);
                    const size_t off = (size_t)(m + half * 8) * HIDc + n;
                    *(__nv_bfloat162*)(dh + off) = hp;
                    *(__nv_bfloat162*)(dl + off) = lp;
                }
            }
        }
    }
}

// ---------------------------------------------------------------------------
// Scores on tensor cores, one-shot K: full HD=64 in smem (one cp.async phase),
// then 4 uninterrupted MMA steps. Epilogue: exp(s/8 + beta*sim), mask, rowsum.
// Streaming stores for e (not re-read via L2 soon; preserves L2 for sim).
// Dynamic smem: 4 tiles x (128 x 72 halves) = 73728 B.
// ---------------------------------------------------------------------------
constexpr int SC_SMEM = 4 * 128 * 72 * 2;   // 73728

__global__ __launch_bounds__(256) void scores_mma_kernel(
    const float* __restrict__ sim, const int* __restrict__ amask,
    const float* __restrict__ beta_p, float* __restrict__ attn)
{
    extern __shared__ __align__(128) char dsm[];
    constexpr int LDT = 72;                 // halves; 144 B row stride
    constexpr int TILE = 128 * LDT * 2;     // 18432 B
    const uint32_t sb = smem_u32(dsm);

    const int tid = threadIdx.x, wid = tid >> 5, lane = tid & 31;
    const int bh = blockIdx.z, b = bh >> 4, h = bh & 15;
    const int q0 = blockIdx.y * 128, k0 = blockIdx.x * 128;
    const int wm = wid >> 2, wn = wid & 3;

    {
        const __nv_bfloat16* srcs[4] = {g_qkvh, g_qkvl, g_qkvh + CHUNK, g_qkvl + CHUNK};
        const int rb[4] = {q0, q0, k0, k0};
        #pragma unroll
        for (int L = 0; L < 16; L++) {
            const int e = tid + L * 256;
            const int t = e >> 10, r = (e >> 3) & 127, c = e & 7;
            const size_t g = ((size_t)b * Sc + rb[t] + r) * HIDc + h * HDc + c * 8;
            CPA(sb + t * TILE + r * (LDT * 2) + c * 16, srcs[t] + g);
        }
        CPC(); CPW(0);
    }
    __syncthreads();

    float acc[4][4][4];
    #pragma unroll
    for (int i = 0; i < 4; i++)
        #pragma unroll
        for (int j = 0; j < 4; j++)
            #pragma unroll
            for (int t = 0; t < 4; t++) acc[i][j][t] = 0.0f;

    const uint32_t aoff = ((lane & 15) * LDT + (lane >> 4) * 8) * 2;
    const uint32_t boff = ((lane & 7) * LDT + ((lane >> 3) & 1) * 8) * 2;
    const uint32_t aQh = sb, aQl = sb + TILE, aKh = sb + 2 * TILE, aKl = sb + 3 * TILE;

    #pragma unroll
    for (int ks = 0; ks < 64; ks += 16) {
        uint32_t af[4][4], bhf[4][2], blf[4][2];
        #pragma unroll
        for (int i = 0; i < 4; i++)
            LDSM4(af[i], aQh + ((wm * 64 + i * 16) * LDT + ks) * 2 + aoff);
        #pragma unroll
        for (int j = 0; j < 4; j++)
            LDSM2(bhf[j], aKh + ((wn * 32 + j * 8) * LDT + ks) * 2 + boff);
        #pragma unroll
        for (int i = 0; i < 4; i++)
            #pragma unroll
            for (int j = 0; j < 4; j++) MMA16816(acc[i][j], af[i], bhf[j]);
        #pragma unroll
        for (int j = 0; j < 4; j++)
            LDSM2(blf[j], aKl + ((wn * 32 + j * 8) * LDT + ks) * 2 + boff);
        #pragma unroll
        for (int i = 0; i < 4; i++)
            #pragma unroll
            for (int j = 0; j < 4; j++) MMA16816(acc[i][j], af[i], blf[j]);
        #pragma unroll
        for (int i = 0; i < 4; i++)
            LDSM4(af[i], aQl + ((wm * 64 + i * 16) * LDT + ks) * 2 + aoff);
        #pragma unroll
        for (int i = 0; i < 4; i++)
            #pragma unroll
            for (int j = 0; j < 4; j++) MMA16816(acc[i][j], af[i], bhf[j]);
    }

    const float beta = *beta_p;
    const int er = lane >> 2, ec = (lane & 3) * 2;

    int2 mk[4];
    #pragma unroll
    for (int j = 0; j < 4; j++)
        mk[j] = *(const int2*)(amask + (size_t)b * Sc + k0 + wn * 32 + j * 8 + ec);

    #pragma unroll
    for (int i = 0; i < 4; i++) {
        #pragma unroll
        for (int half = 0; half < 2; half++) {
            const int q = q0 + wm * 64 + i * 16 + half * 8 + er;
            const float* simp = sim + ((size_t)b * Sc + q) * Sc + k0 + wn * 32;
            float* ap = attn + ((size_t)bh * Sc + q) * Sc + k0 + wn * 32;
            float rs = 0.0f;
            #pragma unroll
            for (int j = 0; j < 4; j++) {
                const float2 sv = *(const float2*)(simp + j * 8 + ec);
                const float a0 = acc[i][j][half * 2 + 0];
                const float a1 = acc[i][j][half * 2 + 1];
                const float e0 = (mk[j].x == 0) ? 0.0f : __expf(fmaf(beta, sv.x, a0 * 0.125f));
                const float e1 = (mk[j].y == 0) ? 0.0f : __expf(fmaf(beta, sv.y, a1 * 0.125f));
                __stcs((float2*)(ap + j * 8 + ec), make_float2(e0, e1));
                rs += e0 + e1;
            }
            rs += __shfl_xor_sync(0xffffffffu, rs, 1);
            rs += __shfl_xor_sync(0xffffffffu, rs, 2);
            if ((lane & 3) == 0) atomicAdd(&g_rowsum[(size_t)bh * Sc + q], rs);
        }
    }
}

// ---------------------------------------------------------------------------
// AV on tensor cores, fully double-buffered cp.async staging:
// e tile + V tiles for kc+1 issued at loop top (fly during normalize + MMA).
// Normalize: w = e*inv -> streaming STG (final weights) + bf16 split to smem.
// Dynamic smem layout (76288 B):
//   [0)      stag : 2 x 128 x 36 fp32   (36864)
//   [36864)  sWh  : 128 x 40 halves     (10240)
//   [47104)  sWl  : 128 x 40 halves     (10240)
//   [57344)  V    : 2 x (hi 4608 + lo 4608)  (18432)
//   [75776)  inv  : 128 fp32            (512)
// ---------------------------------------------------------------------------
constexpr int AV_SMEM = 76288;

__global__ __launch_bounds__(256) void av_mma_kernel(float* __restrict__ attn)
{
    extern __shared__ __align__(128) char dsm[];
    constexpr int LDA = 40;   // halves (80 B)
    constexpr int LDV = 72;   // halves (144 B)
    constexpr uint32_t STAGB = 18432;
    constexpr uint32_t OF_WH = 36864, OF_WL = 47104, OF_V = 57344, OF_INV = 75776;
    constexpr uint32_t VBUF = 9216, OF_VL = 4608;
    const uint32_t sb = smem_u32(dsm);
    float* s_inv = (float*)(dsm + OF_INV);

    const int tid = threadIdx.x, wid = tid >> 5, lane = tid & 31;
    const int bh = blockIdx.z, b = bh >> 4, h = bh & 15;
    const int q0 = blockIdx.x * 128;
    const int wm = wid >> 2, wn = wid & 3;

    if (tid < 128) s_inv[tid] = 1.0f / g_rowsum[(size_t)bh * Sc + q0 + tid];

    float* Abase = attn + ((size_t)bh * Sc + q0) * Sc;
    const __nv_bfloat16* Vbh = g_qkvh + 2 * CHUNK + (size_t)b * Sc * HIDc + h * HDc;
    const __nv_bfloat16* Vbl = g_qkvl + 2 * CHUNK + (size_t)b * Sc * HIDc + h * HDc;

    const int sr = tid >> 3, sc = tid & 7;
    const int vr = tid >> 3, vc = tid & 7;

    auto issue = [&](int kc, int buf) {
        const int kb = kc * 32;
        const uint32_t stb = sb + buf * STAGB;
        #pragma unroll
        for (int L = 0; L < 4; L++) {
            const int r = sr + L * 32;
            CPA(stb + r * 144 + sc * 16, Abase + (size_t)r * Sc + kb + sc * 4);
        }
        const size_t gv = (size_t)(kb + vr) * HIDc + vc * 8;
        CPA(sb + OF_V + buf * VBUF + vr * 144 + vc * 16, Vbh + gv);
        CPA(sb + OF_V + buf * VBUF + OF_VL + vr * 144 + vc * 16, Vbl + gv);
    };

    issue(0, 0); CPC();

    const uint32_t aoff = ((lane & 15) * LDA + (lane >> 4) * 8) * 2;

    float acc[4][2][4];
    #pragma unroll
    for (int i = 0; i < 4; i++)
        #pragma unroll
        for (int j = 0; j < 2; j++)
            #pragma unroll
            for (int t = 0; t < 4; t++) acc[i][j][t] = 0.0f;

    for (int kc = 0; kc < 64; kc++) {
        const int cur = kc & 1;
        if (kc < 63) { issue(kc + 1, cur ^ 1); CPC(); CPW(1); }
        else         { CPW(0); }
        __syncthreads();

        // Normalize staging -> streaming STG of final weights + bf16 split.
        const char* stg = dsm + cur * STAGB;
        #pragma unroll
        for (int L = 0; L < 4; L++) {
            const int e = tid + L * 256;
            const int ar = e >> 3, ac = (e & 7) * 4;
            float4 av = *(const float4*)(stg + ar * 144 + ac * 4);
            const float iv = s_inv[ar];
            av.x *= iv; av.y *= iv; av.z *= iv; av.w *= iv;
            __stcs((float4*)(Abase + (size_t)ar * Sc + kc * 32 + ac), av);
            __nv_bfloat16 h0, h1, h2, h3, l0, l1, l2, l3;
            split2(av.x, h0, l0); split2(av.y, h1, l1);
            split2(av.z, h2, l2); split2(av.w, h3, l3);
            __nv_bfloat162 hp0(h0, h1), hp1(h2, h3), lp0(l0, l1), lp1(l2, l3);
            *(__nv_bfloat162*)(dsm + OF_WH + (ar * LDA + ac) * 2)     = hp0;
            *(__nv_bfloat162*)(dsm + OF_WH + (ar * LDA + ac + 2) * 2) = hp1;
            *(__nv_bfloat162*)(dsm + OF_WL + (ar * LDA + ac) * 2)     = lp0;
            *(__nv_bfloat162*)(dsm + OF_WL + (ar * LDA + ac + 2) * 2) = lp1;
        }
        __syncthreads();

        const uint32_t vb0 = sb + OF_V + cur * VBUF;
        #pragma unroll
        for (int ks = 0; ks < 32; ks += 16) {
            uint32_t ah[4][4], bhf[2][2], blf[2][2];
            #pragma unroll
            for (int i = 0; i < 4; i++)
                LDSM4(ah[i], sb + OF_WH + ((wm * 64 + i * 16) * LDA + ks) * 2 + aoff);
            #pragma unroll
            for (int j = 0; j < 2; j++) {
                const uint32_t vbo = ((ks + (lane & 15)) * LDV + wn * 16 + j * 8) * 2;
                LDSM2T(bhf[j], vb0 + vbo);
                LDSM2T(blf[j], vb0 + OF_VL + vbo);
            }
            #pragma unroll
            for (int i = 0; i < 4; i++)
                #pragma unroll
                for (int j = 0; j < 2; j++) MMA16816(acc[i][j], ah[i], bhf[j]);
            #pragma unroll
            for (int i = 0; i < 4; i++)
                #pragma unroll
                for (int j = 0; j < 2; j++) MMA16816(acc[i][j], ah[i], blf[j]);
            #pragma unroll
            for (int i = 0; i < 4; i++)
                LDSM4(ah[i], sb + OF_WL + ((wm * 64 + i * 16) * LDA + ks) * 2 + aoff);
            #pragma unroll
            for (int i = 0; i < 4; i++)
                #pragma unroll
                for (int j = 0; j < 2; j++) MMA16816(acc[i][j], ah[i], bhf[j]);
        }
        __syncthreads();
    }

    // Epilogue: ctx split bf16 write. ctx[b, q, h*64 + d]
    const int er = lane >> 2, ec = (lane & 3) * 2;
    #pragma unroll
    for (int j = 0; j < 2; j++) {
        const int d = h * HDc + wn * 16 + j * 8 + ec;
        #pragma unroll
        for (int i = 0; i < 4; i++) {
            const int q = q0 + wm * 64 + i * 16 + er;
            #pragma unroll
            for (int half = 0; half < 2; half++) {
                const float c0 = acc[i][j][half * 2 + 0];
                const float c1 = acc[i][j][half * 2 + 1];
                __nv_bfloat16 h0, h1, l0, l1;
                split2(c0, h0, l0); split2(c1, h1, l1);
                __nv_bfloat162 hp(h0, h1), lp(l0, l1);
                const size_t off = ((size_t)b * Sc + q + half * 8) * HIDc + d;
                *(__nv_bfloat162*)(g_ch + off) = hp;
                *(__nv_bfloat162*)(g_cl + off) = lp;
            }
        }
    }
}

// ---------------------------------------------------------------------------
// Launcher
// ---------------------------------------------------------------------------
extern "C" void kernel_launch(void* const* d_in, const int* in_sizes, int n_in,
                              void* d_out, int out_size)
{
    const float* query = (const float*)d_in[0];
    const float* key   = (const float*)d_in[1];
    const float* value = (const float*)d_in[2];
    const int*   amask = (const int*)  d_in[3];
    const float* sim   = (const float*)d_in[4];
    const float* Wq    = (const float*)d_in[5];
    const float* bq    = (const float*)d_in[6];
    const float* Wk    = (const float*)d_in[7];
    const float* bk    = (const float*)d_in[8];
    const float* Wv    = (const float*)d_in[9];
    const float* bv    = (const float*)d_in[10];
    const float* Wo    = (const float*)d_in[11];
    const float* bo    = (const float*)d_in[12];
    const float* beta  = (const float*)d_in[13];

    float* out  = (float*)d_out;
    float* attn = out + CHUNK;   // attention_weights region [B,NH,S,S]

    cudaFuncSetAttribute(gemm_bf16x3,
                         cudaFuncAttributeMaxDynamicSharedMemorySize, GEMM_SMEM);
    cudaFuncSetAttribute(scores_mma_kernel,
                         cudaFuncAttributeMaxDynamicSharedMemorySize, SC_SMEM);
    cudaFuncSetAttribute(av_mma_kernel,
                         cudaFuncAttributeMaxDynamicSharedMemorySize, AV_SMEM);

    // One conversion pass (inputs + weights + rowsum zero).
    convert_all<<<CVT_BLOCKS, 256>>>(query, key, value, Wq, Wk, Wv, Wo);

    // QKV projections in one launch -> split bf16 Q,K,V.
    dim3 gq(HIDc / 128, Mtot / 128, 3);       // (8, 32, 3)
    gemm_bf16x3<<<gq, 256, GEMM_SMEM>>>(bq, bk, bv, nullptr, 1);

    // Scores + exp + rowsum on tensor cores.
    dim3 gs(Sc / 128, Sc / 128, Bc * NHc);    // (16, 16, 32)
    scores_mma_kernel<<<gs, 256, SC_SMEM>>>(sim, amask, beta, attn);

    // Normalize + AV on tensor cores -> ctx split bf16.
    dim3 ga(Sc / 128, 1, Bc * NHc);           // (16, 1, 32)
    av_mma_kernel<<<ga, 256, AV_SMEM>>>(attn);

    // Output projection (fp32 out).
    dim3 go(HIDc / 128, Mtot / 128, 1);       // (8, 32)
    gemm_bf16x3<<<go, 256, GEMM_SMEM>>>(bo, nullptr, nullptr, out, 0);
}

// round 12
// speedup vs baseline: 2.1458x; 1.0809x over previous
#include <cuda_runtime.h>
#include <cuda_bf16.h>
#include <cstdint>

// Problem constants
constexpr int Bc   = 2;
constexpr int Sc   = 2048;
constexpr int HIDc = 1024;
constexpr int NHc  = 16;
constexpr int HDc  = 64;           // HID / NH
constexpr int Mtot = Bc * Sc;      // 4096
constexpr size_t CHUNK = (size_t)Bc * Sc * HIDc;  // 4,194,304 floats
constexpr size_t WSZ   = (size_t)HIDc * HIDc;     // 1,048,576
constexpr int NROWS = Bc * NHc * Sc;              // 65536 softmax rows

__device__ float g_rowsum[NROWS];
// bf16 split-precision scratch
__device__ __nv_bfloat16 g_inh[3 * CHUNK];   // query,key,value inputs hi
__device__ __nv_bfloat16 g_inl[3 * CHUNK];   // lo
__device__ __nv_bfloat16 g_wh[4 * WSZ];      // Wq,Wk,Wv,Wo hi
__device__ __nv_bfloat16 g_wl[4 * WSZ];      // lo
__device__ __nv_bfloat16 g_qkvh[3 * CHUNK];  // projected Q,K,V hi
__device__ __nv_bfloat16 g_qkvl[3 * CHUNK];  // lo
__device__ __nv_bfloat16 g_ch[CHUNK];        // ctx hi
__device__ __nv_bfloat16 g_cl[CHUNK];        // ctx lo

__device__ __forceinline__ uint32_t smem_u32(const void* p) {
    uint32_t a;
    asm("{ .reg .u64 t; cvta.to.shared.u64 t, %1; cvt.u32.u64 %0, t; }"
        : "=r"(a) : "l"(p));
    return a;
}

#define LDSM4(r, addr) \
    asm volatile("ldmatrix.sync.aligned.m8n8.x4.shared.b16 {%0,%1,%2,%3}, [%4];" \
        : "=r"((r)[0]), "=r"((r)[1]), "=r"((r)[2]), "=r"((r)[3]) : "r"(addr))
#define LDSM2(r, addr) \
    asm volatile("ldmatrix.sync.aligned.m8n8.x2.shared.b16 {%0,%1}, [%2];" \
        : "=r"((r)[0]), "=r"((r)[1]) : "r"(addr))
#define LDSM2T(r, addr) \
    asm volatile("ldmatrix.sync.aligned.m8n8.x2.trans.shared.b16 {%0,%1}, [%2];" \
        : "=r"((r)[0]), "=r"((r)[1]) : "r"(addr))
#define MMA16816(c, a, b) \
    asm volatile("mma.sync.aligned.m16n8k16.row.col.f32.bf16.bf16.f32 " \
        "{%0,%1,%2,%3}, {%4,%5,%6,%7}, {%8,%9}, {%0,%1,%2,%3};" \
        : "+f"((c)[0]), "+f"((c)[1]), "+f"((c)[2]), "+f"((c)[3]) \
        : "r"((a)[0]), "r"((a)[1]), "r"((a)[2]), "r"((a)[3]), \
          "r"((b)[0]), "r"((b)[1]))
#define CPA(dst, src) \
    asm volatile("cp.async.cg.shared.global [%0], [%1], 16;" :: "r"(dst), "l"(src))
#define CPC() asm volatile("cp.async.commit_group;")
#define CPW(n) asm volatile("cp.async.wait_group %0;" :: "n"(n))

__device__ __forceinline__ void split2(float x, __nv_bfloat16& h, __nv_bfloat16& l) {
    h = __float2bfloat16(x);
    l = __float2bfloat16(x - __bfloat162float(h));
}

// ---------------------------------------------------------------------------
// Single merged conversion kernel (inputs + weights + rowsum zero).
// ---------------------------------------------------------------------------
constexpr int CVT_BLOCKS = (int)((3 * CHUNK + 4 * WSZ) / 1024);

__global__ __launch_bounds__(256) void convert_all(
    const float* __restrict__ q, const float* __restrict__ k,
    const float* __restrict__ v, const float* __restrict__ wq,
    const float* __restrict__ wk, const float* __restrict__ wv,
    const float* __restrict__ wo)
{
    const size_t gid = (size_t)blockIdx.x * 256 + threadIdx.x;
    if (gid < NROWS / 4)
        ((float4*)g_rowsum)[gid] = make_float4(0.f, 0.f, 0.f, 0.f);

    const size_t i = gid * 4;
    const float* src;
    __nv_bfloat16 *h, *l;
    size_t off;
    if (i < 3 * CHUNK) {
        const int s = (int)(i / CHUNK);
        off = i - (size_t)s * CHUNK;
        src = (s == 0) ? q : (s == 1) ? k : v;
        h = g_inh + (size_t)s * CHUNK; l = g_inl + (size_t)s * CHUNK;
    } else {
        const size_t i2 = i - 3 * CHUNK;
        const int s = (int)(i2 / WSZ);
        off = i2 - (size_t)s * WSZ;
        src = (s == 0) ? wq : (s == 1) ? wk : (s == 2) ? wv : wo;
        h = g_wh + (size_t)s * WSZ; l = g_wl + (size_t)s * WSZ;
    }

    float4 x = *(const float4*)(src + off);
    __nv_bfloat16 h0, h1, h2, h3, l0, l1, l2, l3;
    split2(x.x, h0, l0); split2(x.y, h1, l1);
    split2(x.z, h2, l2); split2(x.w, h3, l3);
    __nv_bfloat162 hp0(h0, h1), hp1(h2, h3), lp0(l0, l1), lp1(l2, l3);
    uint2 hv, lv;
    hv.x = *(uint32_t*)&hp0; hv.y = *(uint32_t*)&hp1;
    lv.x = *(uint32_t*)&lp0; lv.y = *(uint32_t*)&lp1;
    *(uint2*)(h + off) = hv;
    *(uint2*)(l + off) = lv;
}

// ---------------------------------------------------------------------------
// mma.sync bf16x3 GEMM with cp.async double buffering. (unchanged from R11)
// ---------------------------------------------------------------------------
constexpr int GEMM_SMEM = 2 * 4 * 128 * 40 * 2;   // 81920

__global__ __launch_bounds__(256) void gemm_bf16x3(
    const float* __restrict__ b0, const float* __restrict__ b1,
    const float* __restrict__ b2, float* __restrict__ Cext, int qkv_mode)
{
    int a_sel, w_sel, osel;
    const float* bias;
    if (qkv_mode) {
        a_sel = w_sel = osel = blockIdx.z;
        bias = (blockIdx.z == 0) ? b0 : (blockIdx.z == 1) ? b1 : b2;
    } else {
        a_sel = 3; w_sel = 3; osel = -1; bias = b0;
    }
    const __nv_bfloat16* Ah = (a_sel < 3) ? g_inh + (size_t)a_sel * CHUNK : g_ch;
    const __nv_bfloat16* Al = (a_sel < 3) ? g_inl + (size_t)a_sel * CHUNK : g_cl;
    const __nv_bfloat16* Wh = g_wh + (size_t)w_sel * WSZ;
    const __nv_bfloat16* Wl = g_wl + (size_t)w_sel * WSZ;

    extern __shared__ __align__(128) char dsm[];
    constexpr int LDT = 40;
    constexpr int TILE = 128 * LDT * 2;
    constexpr int BUF  = 4 * TILE;
    const uint32_t sb = smem_u32(dsm);

    const int tid = threadIdx.x, wid = tid >> 5, lane = tid & 31;
    const int m0 = blockIdx.y * 128, n0 = blockIdx.x * 128;
    const int wm = wid >> 2, wn = wid & 3;

    float acc[4][4][4];
    #pragma unroll
    for (int i = 0; i < 4; i++)
        #pragma unroll
        for (int j = 0; j < 4; j++)
            #pragma unroll
            for (int t = 0; t < 4; t++) acc[i][j][t] = 0.0f;

    const int r0 = tid >> 2, c0v = (tid & 3) * 8;
    const int r1 = r0 + 64;
    const uint32_t sOff0 = r0 * (LDT * 2) + c0v * 2;
    const uint32_t sOff1 = r1 * (LDT * 2) + c0v * 2;

    const uint32_t aoff = ((lane & 15) * LDT + (lane >> 4) * 8) * 2;
    const uint32_t boff = ((lane & 7) * LDT + ((lane >> 3) & 1) * 8) * 2;

    auto issue = [&](int kc, int buf) {
        const int kb = kc * 32;
        const uint32_t base = sb + buf * BUF;
        const size_t gA0 = (size_t)(m0 + r0) * HIDc + kb + c0v;
        const size_t gA1 = (size_t)(m0 + r1) * HIDc + kb + c0v;
        const size_t gB0 = (size_t)(n0 + r0) * HIDc + kb + c0v;
        const size_t gB1 = (size_t)(n0 + r1) * HIDc + kb + c0v;
        CPA(base + 0 * TILE + sOff0, Ah + gA0);
        CPA(base + 0 * TILE + sOff1, Ah + gA1);
        CPA(base + 1 * TILE + sOff0, Al + gA0);
        CPA(base + 1 * TILE + sOff1, Al + gA1);
        CPA(base + 2 * TILE + sOff0, Wh + gB0);
        CPA(base + 2 * TILE + sOff1, Wh + gB1);
        CPA(base + 3 * TILE + sOff0, Wl + gB0);
        CPA(base + 3 * TILE + sOff1, Wl + gB1);
    };

    issue(0, 0); CPC();

    for (int kc = 0; kc < 32; kc++) {
        const int cur = kc & 1;
        if (kc < 31) { issue(kc + 1, cur ^ 1); CPC(); CPW(1); }
        else         { CPW(0); }
        __syncthreads();

        const uint32_t bA = sb + cur * BUF;
        #pragma unroll
        for (int ks = 0; ks < 32; ks += 16) {
            uint32_t af[4][4], bh[4][2], bl[4][2];
            #pragma unroll
            for (int i = 0; i < 4; i++)
                LDSM4(af[i], bA + 0 * TILE + ((wm * 64 + i * 16) * LDT + ks) * 2 + aoff);
            #pragma unroll
            for (int j = 0; j < 4; j++)
                LDSM2(bh[j], bA + 2 * TILE + ((wn * 32 + j * 8) * LDT + ks) * 2 + boff);
            #pragma unroll
            for (int i = 0; i < 4; i++)
                #pragma unroll
                for (int j = 0; j < 4; j++) MMA16816(acc[i][j], af[i], bh[j]);
            #pragma unroll
            for (int j = 0; j < 4; j++)
                LDSM2(bl[j], bA + 3 * TILE + ((wn * 32 + j * 8) * LDT + ks) * 2 + boff);
            #pragma unroll
            for (int i = 0; i < 4; i++)
                #pragma unroll
                for (int j = 0; j < 4; j++) MMA16816(acc[i][j], af[i], bl[j]);
            #pragma unroll
            for (int i = 0; i < 4; i++)
                LDSM4(af[i], bA + 1 * TILE + ((wm * 64 + i * 16) * LDT + ks) * 2 + aoff);
            #pragma unroll
            for (int i = 0; i < 4; i++)
                #pragma unroll
                for (int j = 0; j < 4; j++) MMA16816(acc[i][j], af[i], bh[j]);
        }
        __syncthreads();
    }

    const int er = lane >> 2, ec = (lane & 3) * 2;
    if (osel < 0) {
        #pragma unroll
        for (int j = 0; j < 4; j++) {
            const int n = n0 + wn * 32 + j * 8 + ec;
            const float bx = bias[n], by = bias[n + 1];
            #pragma unroll
            for (int i = 0; i < 4; i++) {
                const int m = m0 + wm * 64 + i * 16 + er;
                *(float2*)(Cext + (size_t)m * HIDc + n) =
                    make_float2(acc[i][j][0] + bx, acc[i][j][1] + by);
                *(float2*)(Cext + (size_t)(m + 8) * HIDc + n) =
                    make_float2(acc[i][j][2] + bx, acc[i][j][3] + by);
            }
        }
    } else {
        __nv_bfloat16* dh = g_qkvh + (size_t)osel * CHUNK;
        __nv_bfloat16* dl = g_qkvl + (size_t)osel * CHUNK;
        #pragma unroll
        for (int j = 0; j < 4; j++) {
            const int n = n0 + wn * 32 + j * 8 + ec;
            const float bx = bias[n], by = bias[n + 1];
            #pragma unroll
            for (int i = 0; i < 4; i++) {
                const int m = m0 + wm * 64 + i * 16 + er;
                #pragma unroll
                for (int half = 0; half < 2; half++) {
                    const float c0 = acc[i][j][half * 2 + 0] + bx;
                    const float c1 = acc[i][j][half * 2 + 1] + by;
                    __nv_bfloat16 h0, h1, l0, l1;
                    split2(c0, h0, l0); split2(c1, h1, l1);
                    __nv_bfloat162 hp(h0, h1), lp(l0, l1);
                    const size_t off = (size_t)(m + half * 8) * HIDc + n;
                    *(__nv_bfloat162*)(dh + off) = hp;
                    *(__nv_bfloat162*)(dl + off) = lp;
                }
            }
        }
    }
}

// ---------------------------------------------------------------------------
// Scores on tensor cores. Grid: (bh, q, k) with bh FASTEST so the 32 blocks
// sharing a (q,k) sim tile run concurrently -> sim served from L2 (16 heads).
// ---------------------------------------------------------------------------
constexpr int SC_SMEM = 4 * 128 * 72 * 2;   // 73728

__global__ __launch_bounds__(256) void scores_mma_kernel(
    const float* __restrict__ sim, const int* __restrict__ amask,
    const float* __restrict__ beta_p, float* __restrict__ attn)
{
    extern __shared__ __align__(128) char dsm[];
    constexpr int LDT = 72;
    constexpr int TILE = 128 * LDT * 2;
    const uint32_t sb = smem_u32(dsm);

    const int tid = threadIdx.x, wid = tid >> 5, lane = tid & 31;
    const int bh = blockIdx.x, b = bh >> 4, h = bh & 15;
    const int q0 = blockIdx.y * 128, k0 = blockIdx.z * 128;
    const int wm = wid >> 2, wn = wid & 3;

    {
        const __nv_bfloat16* srcs[4] = {g_qkvh, g_qkvl, g_qkvh + CHUNK, g_qkvl + CHUNK};
        const int rb[4] = {q0, q0, k0, k0};
        #pragma unroll
        for (int L = 0; L < 16; L++) {
            const int e = tid + L * 256;
            const int t = e >> 10, r = (e >> 3) & 127, c = e & 7;
            const size_t g = ((size_t)b * Sc + rb[t] + r) * HIDc + h * HDc + c * 8;
            CPA(sb + t * TILE + r * (LDT * 2) + c * 16, srcs[t] + g);
        }
        CPC(); CPW(0);
    }
    __syncthreads();

    float acc[4][4][4];
    #pragma unroll
    for (int i = 0; i < 4; i++)
        #pragma unroll
        for (int j = 0; j < 4; j++)
            #pragma unroll
            for (int t = 0; t < 4; t++) acc[i][j][t] = 0.0f;

    const uint32_t aoff = ((lane & 15) * LDT + (lane >> 4) * 8) * 2;
    const uint32_t boff = ((lane & 7) * LDT + ((lane >> 3) & 1) * 8) * 2;
    const uint32_t aQh = sb, aQl = sb + TILE, aKh = sb + 2 * TILE, aKl = sb + 3 * TILE;

    #pragma unroll
    for (int ks = 0; ks < 64; ks += 16) {
        uint32_t af[4][4], bhf[4][2], blf[4][2];
        #pragma unroll
        for (int i = 0; i < 4; i++)
            LDSM4(af[i], aQh + ((wm * 64 + i * 16) * LDT + ks) * 2 + aoff);
        #pragma unroll
        for (int j = 0; j < 4; j++)
            LDSM2(bhf[j], aKh + ((wn * 32 + j * 8) * LDT + ks) * 2 + boff);
        #pragma unroll
        for (int i = 0; i < 4; i++)
            #pragma unroll
            for (int j = 0; j < 4; j++) MMA16816(acc[i][j], af[i], bhf[j]);
        #pragma unroll
        for (int j = 0; j < 4; j++)
            LDSM2(blf[j], aKl + ((wn * 32 + j * 8) * LDT + ks) * 2 + boff);
        #pragma unroll
        for (int i = 0; i < 4; i++)
            #pragma unroll
            for (int j = 0; j < 4; j++) MMA16816(acc[i][j], af[i], blf[j]);
        #pragma unroll
        for (int i = 0; i < 4; i++)
            LDSM4(af[i], aQl + ((wm * 64 + i * 16) * LDT + ks) * 2 + aoff);
        #pragma unroll
        for (int i = 0; i < 4; i++)
            #pragma unroll
            for (int j = 0; j < 4; j++) MMA16816(acc[i][j], af[i], bhf[j]);
    }

    const float beta = *beta_p;
    const int er = lane >> 2, ec = (lane & 3) * 2;

    int2 mk[4];
    #pragma unroll
    for (int j = 0; j < 4; j++)
        mk[j] = *(const int2*)(amask + (size_t)b * Sc + k0 + wn * 32 + j * 8 + ec);

    #pragma unroll
    for (int i = 0; i < 4; i++) {
        #pragma unroll
        for (int half = 0; half < 2; half++) {
            const int q = q0 + wm * 64 + i * 16 + half * 8 + er;
            const float* simp = sim + ((size_t)b * Sc + q) * Sc + k0 + wn * 32;
            float* ap = attn + ((size_t)bh * Sc + q) * Sc + k0 + wn * 32;
            float rs = 0.0f;
            #pragma unroll
            for (int j = 0; j < 4; j++) {
                const float2 sv = *(const float2*)(simp + j * 8 + ec);
                const float a0 = acc[i][j][half * 2 + 0];
                const float a1 = acc[i][j][half * 2 + 1];
                const float e0 = (mk[j].x == 0) ? 0.0f : __expf(fmaf(beta, sv.x, a0 * 0.125f));
                const float e1 = (mk[j].y == 0) ? 0.0f : __expf(fmaf(beta, sv.y, a1 * 0.125f));
                __stcs((float2*)(ap + j * 8 + ec), make_float2(e0, e1));
                rs += e0 + e1;
            }
            rs += __shfl_xor_sync(0xffffffffu, rs, 1);
            rs += __shfl_xor_sync(0xffffffffu, rs, 2);
            if ((lane & 3) == 0) atomicAdd(&g_rowsum[(size_t)bh * Sc + q], rs);
        }
    }
}

// ---------------------------------------------------------------------------
// AV on tensor cores. BQ=64 tiles (smem 47 KB, ~4 CTA/SM) for latency hiding
// on the DRAM-bound e-read/w-write. 8 warps 2(m) x 4(n), warp tile 32x16.
// Dynamic smem (47360 B):
//   [0)      stag : 2 x 64 x 36 fp32    (18432)
//   [18432)  sWh  : 64 x 40 halves      (5120)
//   [23552)  sWl  : 64 x 40 halves      (5120)
//   [28672)  V    : 2 x (hi 4608 + lo 4608)  (18432)
//   [47104)  inv  : 64 fp32             (256)
// ---------------------------------------------------------------------------
constexpr int AV_SMEM = 47360;

__global__ __launch_bounds__(256) void av_mma_kernel(float* __restrict__ attn)
{
    extern __shared__ __align__(128) char dsm[];
    constexpr int LDA = 40;   // halves (80 B)
    constexpr int LDV = 72;   // halves (144 B)
    constexpr uint32_t STAGB = 9216;
    constexpr uint32_t OF_WH = 18432, OF_WL = 23552, OF_V = 28672, OF_INV = 47104;
    constexpr uint32_t VBUF = 9216, OF_VL = 4608;
    const uint32_t sb = smem_u32(dsm);
    float* s_inv = (float*)(dsm + OF_INV);

    const int tid = threadIdx.x, wid = tid >> 5, lane = tid & 31;
    const int bh = blockIdx.z, b = bh >> 4, h = bh & 15;
    const int q0 = blockIdx.x * 64;
    const int wm = wid >> 2, wn = wid & 3;

    if (tid < 64) s_inv[tid] = 1.0f / g_rowsum[(size_t)bh * Sc + q0 + tid];

    float* Abase = attn + ((size_t)bh * Sc + q0) * Sc;
    const __nv_bfloat16* Vbh = g_qkvh + 2 * CHUNK + (size_t)b * Sc * HIDc + h * HDc;
    const __nv_bfloat16* Vbl = g_qkvl + 2 * CHUNK + (size_t)b * Sc * HIDc + h * HDc;

    const int sr = tid >> 3, sc = tid & 7;   // 32 rows x 8 col-quads

    auto issue = [&](int kc, int buf) {
        const int kb = kc * 32;
        const uint32_t stb = sb + buf * STAGB;
        #pragma unroll
        for (int L = 0; L < 2; L++) {
            const int r = sr + L * 32;
            CPA(stb + r * 144 + sc * 16, Abase + (size_t)r * Sc + kb + sc * 4);
        }
        const size_t gv = (size_t)(kb + sr) * HIDc + sc * 8;
        CPA(sb + OF_V + buf * VBUF + sr * 144 + sc * 16, Vbh + gv);
        CPA(sb + OF_V + buf * VBUF + OF_VL + sr * 144 + sc * 16, Vbl + gv);
    };

    issue(0, 0); CPC();

    const uint32_t aoff = ((lane & 15) * LDA + (lane >> 4) * 8) * 2;

    float acc[2][2][4];
    #pragma unroll
    for (int i = 0; i < 2; i++)
        #pragma unroll
        for (int j = 0; j < 2; j++)
            #pragma unroll
            for (int t = 0; t < 4; t++) acc[i][j][t] = 0.0f;

    for (int kc = 0; kc < 64; kc++) {
        const int cur = kc & 1;
        if (kc < 63) { issue(kc + 1, cur ^ 1); CPC(); CPW(1); }
        else         { CPW(0); }
        __syncthreads();

        // Normalize staging -> streaming STG of final weights + bf16 split.
        const char* stg = dsm + cur * STAGB;
        #pragma unroll
        for (int L = 0; L < 2; L++) {
            const int e = tid + L * 256;
            const int ar = e >> 3, ac = (e & 7) * 4;
            float4 av = *(const float4*)(stg + ar * 144 + ac * 4);
            const float iv = s_inv[ar];
            av.x *= iv; av.y *= iv; av.z *= iv; av.w *= iv;
            __stcs((float4*)(Abase + (size_t)ar * Sc + kc * 32 + ac), av);
            __nv_bfloat16 h0, h1, h2, h3, l0, l1, l2, l3;
            split2(av.x, h0, l0); split2(av.y, h1, l1);
            split2(av.z, h2, l2); split2(av.w, h3, l3);
            __nv_bfloat162 hp0(h0, h1), hp1(h2, h3), lp0(l0, l1), lp1(l2, l3);
            *(__nv_bfloat162*)(dsm + OF_WH + (ar * LDA + ac) * 2)     = hp0;
            *(__nv_bfloat162*)(dsm + OF_WH + (ar * LDA + ac + 2) * 2) = hp1;
            *(__nv_bfloat162*)(dsm + OF_WL + (ar * LDA + ac) * 2)     = lp0;
            *(__nv_bfloat162*)(dsm + OF_WL + (ar * LDA + ac + 2) * 2) = lp1;
        }
        __syncthreads();

        const uint32_t vb0 = sb + OF_V + cur * VBUF;
        #pragma unroll
        for (int ks = 0; ks < 32; ks += 16) {
            uint32_t ah[2][4], bhf[2][2], blf[2][2];
            #pragma unroll
            for (int i = 0; i < 2; i++)
                LDSM4(ah[i], sb + OF_WH + ((wm * 32 + i * 16) * LDA + ks) * 2 + aoff);
            #pragma unroll
            for (int j = 0; j < 2; j++) {
                const uint32_t vbo = ((ks + (lane & 15)) * LDV + wn * 16 + j * 8) * 2;
                LDSM2T(bhf[j], vb0 + vbo);
                LDSM2T(blf[j], vb0 + OF_VL + vbo);
            }
            #pragma unroll
            for (int i = 0; i < 2; i++)
                #pragma unroll
                for (int j = 0; j < 2; j++) MMA16816(acc[i][j], ah[i], bhf[j]);
            #pragma unroll
            for (int i = 0; i < 2; i++)
                #pragma unroll
                for (int j = 0; j < 2; j++) MMA16816(acc[i][j], ah[i], blf[j]);
            #pragma unroll
            for (int i = 0; i < 2; i++)
                LDSM4(ah[i], sb + OF_WL + ((wm * 32 + i * 16) * LDA + ks) * 2 + aoff);
            #pragma unroll
            for (int i = 0; i < 2; i++)
                #pragma unroll
                for (int j = 0; j < 2; j++) MMA16816(acc[i][j], ah[i], bhf[j]);
        }
        __syncthreads();
    }

    // Epilogue: ctx split bf16 write. ctx[b, q, h*64 + d]
    const int er = lane >> 2, ec = (lane & 3) * 2;
    #pragma unroll
    for (int j = 0; j < 2; j++) {
        const int d = h * HDc + wn * 16 + j * 8 + ec;
        #pragma unroll
        for (int i = 0; i < 2; i++) {
            const int q = q0 + wm * 32 + i * 16 + er;
            #pragma unroll
            for (int half = 0; half < 2; half++) {
                const float c0 = acc[i][j][half * 2 + 0];
                const float c1 = acc[i][j][half * 2 + 1];
                __nv_bfloat16 h0, h1, l0, l1;
                split2(c0, h0, l0); split2(c1, h1, l1);
                __nv_bfloat162 hp(h0, h1), lp(l0, l1);
                const size_t off = ((size_t)b * Sc + q + half * 8) * HIDc + d;
                *(__nv_bfloat162*)(g_ch + off) = hp;
                *(__nv_bfloat162*)(g_cl + off) = lp;
            }
        }
    }
}

// ---------------------------------------------------------------------------
// Launcher
// ---------------------------------------------------------------------------
extern "C" void kernel_launch(void* const* d_in, const int* in_sizes, int n_in,
                              void* d_out, int out_size)
{
    const float* query = (const float*)d_in[0];
    const float* key   = (const float*)d_in[1];
    const float* value = (const float*)d_in[2];
    const int*   amask = (const int*)  d_in[3];
    const float* sim   = (const float*)d_in[4];
    const float* Wq    = (const float*)d_in[5];
    const float* bq    = (const float*)d_in[6];
    const float* Wk    = (const float*)d_in[7];
    const float* bk    = (const float*)d_in[8];
    const float* Wv    = (const float*)d_in[9];
    const float* bv    = (const float*)d_in[10];
    const float* Wo    = (const float*)d_in[11];
    const float* bo    = (const float*)d_in[12];
    const float* beta  = (const float*)d_in[13];

    float* out  = (float*)d_out;
    float* attn = out + CHUNK;   // attention_weights region [B,NH,S,S]

    cudaFuncSetAttribute(gemm_bf16x3,
                         cudaFuncAttributeMaxDynamicSharedMemorySize, GEMM_SMEM);
    cudaFuncSetAttribute(scores_mma_kernel,
                         cudaFuncAttributeMaxDynamicSharedMemorySize, SC_SMEM);
    cudaFuncSetAttribute(av_mma_kernel,
                         cudaFuncAttributeMaxDynamicSharedMemorySize, AV_SMEM);

    // One conversion pass (inputs + weights + rowsum zero).
    convert_all<<<CVT_BLOCKS, 256>>>(query, key, value, Wq, Wk, Wv, Wo);

    // QKV projections in one launch -> split bf16 Q,K,V.
    dim3 gq(HIDc / 128, Mtot / 128, 3);       // (8, 32, 3)
    gemm_bf16x3<<<gq, 256, GEMM_SMEM>>>(bq, bk, bv, nullptr, 1);

    // Scores: bh fastest so 16 heads share each sim tile via L2.
    dim3 gs(Bc * NHc, Sc / 128, Sc / 128);    // (32, 16, 16)
    scores_mma_kernel<<<gs, 256, SC_SMEM>>>(sim, amask, beta, attn);

    // Normalize + AV on tensor cores -> ctx split bf16.
    dim3 ga(Sc / 64, 1, Bc * NHc);            // (32, 1, 32)
    av_mma_kernel<<<ga, 256, AV_SMEM>>>(attn);

    // Output projection (fp32 out).
    dim3 go(HIDc / 128, Mtot / 128, 1);       // (8, 32)
    gemm_bf16x3<<<go, 256, GEMM_SMEM>>>(bo, nullptr, nullptr, out, 0);
}